// round 5
// baseline (speedup 1.0000x reference)
#include <cuda_runtime.h>
#include <math.h>
#include <stdint.h>

#define S_LEN 2048
#define H_DIM 4096
#define NH 32
#define HD 128
#define INNER 16384
#define QKV3 12288   // 3*H

static constexpr float ALPHA   = 7.4833147735478827f;  // sqrt(56)
static constexpr float SCALING = 1.0f;                 // layer_id+1 = 1
static constexpr float COEFF   = 11.313708498984761f;  // sqrt(128)*1
static constexpr float EPS     = 1e-5f;

// ---------------- scratch (device globals; no allocations allowed) ----------
__device__ __align__(1024) float g_res1  [(size_t)S_LEN * H_DIM];
__device__ __align__(1024) float g_qkv   [(size_t)S_LEN * QKV3];
__device__ __align__(1024) float g_ctx   [(size_t)S_LEN * H_DIM];
__device__ __align__(1024) float g_hidden[(size_t)S_LEN * H_DIM];
__device__ __align__(1024) float g_res2  [(size_t)S_LEN * H_DIM];
__device__ __align__(1024) float g_act   [(size_t)S_LEN * INNER];

// ---------------- helpers ----------------
__device__ __forceinline__ float warpSum(float v) {
    #pragma unroll
    for (int o = 16; o > 0; o >>= 1) v += __shfl_xor_sync(0xffffffffu, v, o);
    return v;
}
__device__ __forceinline__ float warpMax(float v) {
    #pragma unroll
    for (int o = 16; o > 0; o >>= 1) v = fmaxf(v, __shfl_xor_sync(0xffffffffu, v, o));
    return v;
}
__device__ __forceinline__ float gelu_tanh(float x) {
    float x3 = x * x * x;
    return 0.5f * x * (1.f + tanhf(0.7978845608028654f * (x + 0.044715f * x3)));
}

// packed 2xfp32 fma: c.lo += a.lo*b.lo ; c.hi += a.hi*b.hi
__device__ __forceinline__ void fma2(unsigned long long& c,
                                     unsigned long long a,
                                     unsigned long long b) {
    asm("fma.rn.f32x2 %0, %1, %2, %0;" : "+l"(c) : "l"(a), "l"(b));
}
__device__ __forceinline__ float pair_sum(unsigned long long c) {
    uint32_t lo, hi;
    asm("mov.b64 {%0,%1}, %2;" : "=r"(lo), "=r"(hi) : "l"(c));
    return __uint_as_float(lo) + __uint_as_float(hi);
}

// ---------------- LayerNorm ----------------
__global__ void ln_kernel(const float* __restrict__ x,
                          const float* __restrict__ w,
                          const float* __restrict__ b,
                          float* __restrict__ out) {
    int row = blockIdx.x;
    int t = threadIdx.x;
    const float* xr = x + (size_t)row * H_DIM;
    float v[16];
    float s = 0.f;
    #pragma unroll
    for (int i = 0; i < 16; i++) { v[i] = xr[t + i * 256]; s += v[i]; }

    __shared__ float sh[8];
    __shared__ float s_mean, s_rstd;
    int lane = t & 31, wid = t >> 5;

    s = warpSum(s);
    if (lane == 0) sh[wid] = s;
    __syncthreads();
    if (t == 0) {
        float tot = 0.f;
        #pragma unroll
        for (int i = 0; i < 8; i++) tot += sh[i];
        s_mean = tot / (float)H_DIM;
    }
    __syncthreads();
    float m = s_mean;

    float vs = 0.f;
    #pragma unroll
    for (int i = 0; i < 16; i++) { float d = v[i] - m; vs += d * d; }
    vs = warpSum(vs);
    __syncthreads();
    if (lane == 0) sh[wid] = vs;
    __syncthreads();
    if (t == 0) {
        float tot = 0.f;
        #pragma unroll
        for (int i = 0; i < 8; i++) tot += sh[i];
        s_rstd = rsqrtf(tot / (float)H_DIM + EPS);
    }
    __syncthreads();
    float r = s_rstd;

    float* orow = out + (size_t)row * H_DIM;
    #pragma unroll
    for (int i = 0; i < 16; i++) {
        int c = t + i * 256;
        orow[c] = (v[i] - m) * r * w[c] + b[c];
    }
}

// ---------------- RoPE (GLM dual rotary), in-place on qkv -------------------
__global__ void rope_kernel(float* __restrict__ qkv,
                            const float* __restrict__ cosc,
                            const float* __restrict__ sinc) {
    int s = blockIdx.x, h = blockIdx.y;
    float* base = qkv + (size_t)s * QKV3 + h * 384;
    __shared__ float buf[256];
    int t = threadIdx.x;
    buf[t] = base[t];
    __syncthreads();

    int isK  = (t >= 128) ? 128 : 0;
    int d    = t & 127;
    int half = d >> 6;
    int dd   = d & 63;

    int pos;
    if (half == 0) pos = (s < S_LEN - 1) ? s : (S_LEN - 2);
    else           pos = (s == S_LEN - 1) ? 1 : 0;

    float c  = cosc[pos * 64 + dd];
    float sn = sinc[pos * 64 + dd];

    int boff = isK + half * 64;
    float x   = buf[boff + dd];
    float rot = (dd < 32) ? -buf[boff + dd + 32] : buf[boff + dd - 32];
    base[t] = x * c + rot * sn;
}

// ---------------- fused attention ----------------
__global__ void attn_kernel(const float* __restrict__ qkv,
                            float* __restrict__ ctx) {
    int q = blockIdx.x, h = blockIdx.y;
    int t = threadIdx.x;
    __shared__ float Qs[HD];
    __shared__ float P[S_LEN];
    __shared__ float sh[4];
    __shared__ float s_max, s_inv;

    const float scale = SCALING / COEFF;
    Qs[t] = qkv[(size_t)q * QKV3 + h * 384 + t] * scale;
    __syncthreads();

    const float* Kbase = qkv + h * 384 + 128;
    float lmax = -1e30f;
    for (int k = t; k < S_LEN; k += 128) {
        const float* Kr = Kbase + (size_t)k * QKV3;
        float acc = 0.f;
        #pragma unroll 8
        for (int d = 0; d < HD; d++) acc += Qs[d] * Kr[d];
        P[k] = acc;
        lmax = fmaxf(lmax, acc);
    }
    int lane = t & 31, wid = t >> 5;
    lmax = warpMax(lmax);
    if (lane == 0) sh[wid] = lmax;
    __syncthreads();
    if (t == 0) s_max = fmaxf(fmaxf(sh[0], sh[1]), fmaxf(sh[2], sh[3]));
    __syncthreads();
    float gmax = s_max;

    float lsum = 0.f;
    for (int k = t; k < S_LEN; k += 128) {
        float e = __expf(P[k] - gmax);
        P[k] = e;
        lsum += e;
    }
    lsum = warpSum(lsum);
    __syncthreads();
    if (lane == 0) sh[wid] = lsum;
    __syncthreads();
    if (t == 0) s_inv = 1.f / (sh[0] + sh[1] + sh[2] + sh[3]);
    __syncthreads();
    float inv = s_inv;

    const float* Vb = qkv + h * 384 + 256 + t;
    float acc = 0.f;
    #pragma unroll 8
    for (int k = 0; k < S_LEN; k++) acc += P[k] * Vb[(size_t)k * QKV3];
    ctx[(size_t)q * H_DIM + h * HD + t] = acc * inv;
}

// ============ packed-f32x2 SIMT GEMM: C[M,N] = A[M,K]*B[N,K]^T ==============
// CTA 128x128, 256 threads, 8 warps (2m x 4n), warp tile 64x32,
// thread tile 8x8 (rows tm+8i, cols tn+4j). K pairs packed in f32x2 halves.
// Smem rows: 16 K-floats + 4 pad = 80B stride -> conflict-free LDS.64.

#define BM 128
#define BN 128
#define BK 16
#define RST 20                        // smem row stride in floats (80 B)
#define TILE_ELEMS (128 * RST)        // 2560 floats per tile

__device__ __forceinline__ void cp_async16(uint32_t sa, const void* g) {
    asm volatile("cp.async.cg.shared.global [%0], [%1], 16;\n" :: "r"(sa), "l"(g));
}
__device__ __forceinline__ void cp_commit() {
    asm volatile("cp.async.commit_group;\n");
}
template <int N>
__device__ __forceinline__ void cp_wait() {
    asm volatile("cp.async.wait_group %0;\n" :: "n"(N));
}

// EPI: 0 = bias ; 1 = gelu(bias+acc) ; 2 = bias+acc + alpha*res
template <int EPI>
__global__ void __launch_bounds__(256, 1)
gemm_f2(const float* __restrict__ A, const float* __restrict__ B,
        const float* __restrict__ bias, const float* __restrict__ res,
        float alpha, float* __restrict__ C, int M, int N, int K) {
    __shared__ float As[2][TILE_ELEMS];
    __shared__ float Bs[2][TILE_ELEMS];

    const int tid  = threadIdx.x;
    const int lane = tid & 31;
    const int wid  = tid >> 5;
    const int wm   = wid & 1;         // 0..1  -> 64-row slab
    const int wn   = wid >> 1;        // 0..3  -> 32-col slab
    const int tm   = lane & 7;        // 0..7
    const int tn   = lane >> 3;       // 0..3

    const int m0 = blockIdx.x * BM;
    const int n0 = blockIdx.y * BN;

    // gmem->smem: 16B chunks; row4 = tid>>2 (0..63), kc = tid&3
    const int row4 = tid >> 2;
    const int kc   = tid & 3;

    const float* Ag = A + (size_t)(m0 + row4) * K + kc * 4;
    const float* Bg = B + (size_t)(n0 + row4) * K + kc * 4;

    const uint32_t sAs = (uint32_t)__cvta_generic_to_shared(&As[0][0]);
    const uint32_t sBs = (uint32_t)__cvta_generic_to_shared(&Bs[0][0]);

    unsigned long long acc[8][8];
    #pragma unroll
    for (int i = 0; i < 8; i++)
        #pragma unroll
        for (int j = 0; j < 8; j++) acc[i][j] = 0ull;

    const int nk = K / BK;

    auto issue = [&](int kt, int b) {
        uint32_t ab = sAs + (uint32_t)b * (TILE_ELEMS * 4);
        uint32_t bb = sBs + (uint32_t)b * (TILE_ELEMS * 4);
        const float* ag = Ag + (size_t)kt * BK;
        const float* bg = Bg + (size_t)kt * BK;
        #pragma unroll
        for (int i = 0; i < 2; i++) {
            cp_async16(ab + (uint32_t)((row4 + 64 * i) * RST + kc * 4) * 4u,
                       ag + (size_t)(64 * i) * K);
            cp_async16(bb + (uint32_t)((row4 + 64 * i) * RST + kc * 4) * 4u,
                       bg + (size_t)(64 * i) * K);
        }
        cp_commit();
    };

    issue(0, 0);

    int buf = 0;
    const int abase = wm * 64 + tm;     // + 8*i rows
    const int bbase = wn * 32 + tn;     // + 4*j rows

    for (int kt = 0; kt < nk; kt++) {
        if (kt + 1 < nk) { issue(kt + 1, buf ^ 1); cp_wait<1>(); }
        else             cp_wait<0>();
        __syncthreads();

        const float* Ab = As[buf];
        const float* Bb = Bs[buf];

        #pragma unroll
        for (int kp = 0; kp < 8; kp++) {          // 8 k-pairs
            unsigned long long a2[8], b2[8];
            #pragma unroll
            for (int i = 0; i < 8; i++)
                a2[i] = *(const unsigned long long*)(Ab + (abase + 8 * i) * RST + kp * 2);
            #pragma unroll
            for (int j = 0; j < 8; j++)
                b2[j] = *(const unsigned long long*)(Bb + (bbase + 4 * j) * RST + kp * 2);
            #pragma unroll
            for (int i = 0; i < 8; i++)
                #pragma unroll
                for (int j = 0; j < 8; j++)
                    fma2(acc[i][j], a2[i], b2[j]);
        }
        __syncthreads();
        buf ^= 1;
    }

    // epilogue
    #pragma unroll
    for (int i = 0; i < 8; i++) {
        const int m = m0 + wm * 64 + tm + 8 * i;
        float* crow = C + (size_t)m * N;
        const float* rrow = res + (size_t)m * N;
        #pragma unroll
        for (int j = 0; j < 8; j++) {
            const int n = n0 + wn * 32 + tn + 4 * j;
            float v = pair_sum(acc[i][j]) + bias[n];
            if (EPI == 1) v = gelu_tanh(v);
            if (EPI == 2) v += alpha * rrow[n];
            crow[n] = v;
        }
    }
}

// ---------------- launch ----------------------------------------------------
extern "C" void kernel_launch(void* const* d_in, const int* in_sizes, int n_in,
                              void* d_out, int out_size) {
    const float* hidden  = (const float*)d_in[0];
    const float* cosc    = (const float*)d_in[4];
    const float* sinc    = (const float*)d_in[5];
    const float* ln1_w   = (const float*)d_in[6];
    const float* ln1_b   = (const float*)d_in[7];
    const float* qkv_w   = (const float*)d_in[8];
    const float* qkv_b   = (const float*)d_in[9];
    const float* dense_w = (const float*)d_in[10];
    const float* dense_b = (const float*)d_in[11];
    const float* ln2_w   = (const float*)d_in[12];
    const float* ln2_b   = (const float*)d_in[13];
    const float* mlp_w1  = (const float*)d_in[14];
    const float* mlp_b1  = (const float*)d_in[15];
    const float* mlp_w2  = (const float*)d_in[16];
    const float* mlp_b2  = (const float*)d_in[17];
    float* out = (float*)d_out;

    float *res1, *qkvb, *ctx, *hid, *res2, *act;
    cudaGetSymbolAddress((void**)&res1, g_res1);
    cudaGetSymbolAddress((void**)&qkvb, g_qkv);
    cudaGetSymbolAddress((void**)&ctx,  g_ctx);
    cudaGetSymbolAddress((void**)&hid,  g_hidden);
    cudaGetSymbolAddress((void**)&res2, g_res2);
    cudaGetSymbolAddress((void**)&act,  g_act);

    // 1. LN1
    ln_kernel<<<S_LEN, 256>>>(hidden, ln1_w, ln1_b, res1);

    // 2. QKV GEMM: [2048,4096] x [12288,4096]^T
    {
        dim3 grid(S_LEN / BM, QKV3 / BN);
        gemm_f2<0><<<grid, 256>>>(res1, qkv_w, qkv_b, res1, 0.f,
                                  qkvb, S_LEN, QKV3, H_DIM);
    }

    // 3. RoPE
    {
        dim3 grid(S_LEN, NH);
        rope_kernel<<<grid, 256>>>(qkvb, cosc, sinc);
    }

    // 4. attention
    {
        dim3 grid(S_LEN, NH);
        attn_kernel<<<grid, 128>>>(qkvb, ctx);
    }

    // 5. dense GEMM + alpha*residual
    {
        dim3 grid(S_LEN / BM, H_DIM / BN);
        gemm_f2<2><<<grid, 256>>>(ctx, dense_w, dense_b, res1, ALPHA,
                                  hid, S_LEN, H_DIM, H_DIM);
    }

    // 6. LN2
    ln_kernel<<<S_LEN, 256>>>(hid, ln2_w, ln2_b, res2);

    // 7. MLP up + gelu
    {
        dim3 grid(S_LEN / BM, INNER / BN);
        gemm_f2<1><<<grid, 256>>>(res2, mlp_w1, mlp_b1, res2, 0.f,
                                  act, S_LEN, INNER, H_DIM);
    }

    // 8. MLP down + alpha*residual -> output
    {
        dim3 grid(S_LEN / BM, H_DIM / BN);
        gemm_f2<2><<<grid, 256>>>(act, mlp_w2, mlp_b2, res2, ALPHA,
                                  out, S_LEN, H_DIM, INNER);
    }
}

// round 6
// speedup vs baseline: 1.0509x; 1.0509x over previous
#include <cuda_runtime.h>
#include <cuda_fp16.h>
#include <math.h>
#include <stdint.h>

#define S_LEN 2048
#define H_DIM 4096
#define NH 32
#define HD 128
#define INNER 16384
#define QKV3 12288   // 3*H

static constexpr float ALPHA   = 7.4833147735478827f;  // sqrt(56)
static constexpr float SCALING = 1.0f;                 // layer_id+1 = 1
static constexpr float COEFF   = 11.313708498984761f;  // sqrt(128)*1
static constexpr float EPS     = 1e-5f;

// ---------------- scratch (device globals; no allocations allowed) ----------
__device__ __align__(1024) float  g_res1  [(size_t)S_LEN * H_DIM];
__device__ __align__(1024) float  g_qkv   [(size_t)S_LEN * QKV3];
__device__ __align__(1024) float  g_hidden[(size_t)S_LEN * H_DIM];
__device__ __align__(1024) float  g_res2  [(size_t)S_LEN * H_DIM];

__device__ __align__(1024) __half g_res1h [(size_t)S_LEN * H_DIM];
__device__ __align__(1024) __half g_res2h [(size_t)S_LEN * H_DIM];
__device__ __align__(1024) __half g_ctxh  [(size_t)S_LEN * H_DIM];
__device__ __align__(1024) __half g_acth  [(size_t)S_LEN * INNER];

__device__ __align__(1024) __half g_qkv_wh  [(size_t)QKV3 * H_DIM];
__device__ __align__(1024) __half g_dense_wh[(size_t)H_DIM * H_DIM];
__device__ __align__(1024) __half g_w1h     [(size_t)INNER * H_DIM];
__device__ __align__(1024) __half g_w2h     [(size_t)H_DIM * INNER];

// ---------------- helpers ----------------
__device__ __forceinline__ float warpSum(float v) {
    #pragma unroll
    for (int o = 16; o > 0; o >>= 1) v += __shfl_xor_sync(0xffffffffu, v, o);
    return v;
}
__device__ __forceinline__ float warpMax(float v) {
    #pragma unroll
    for (int o = 16; o > 0; o >>= 1) v = fmaxf(v, __shfl_xor_sync(0xffffffffu, v, o));
    return v;
}
__device__ __forceinline__ float gelu_tanh(float x) {
    float x3 = x * x * x;
    return 0.5f * x * (1.f + tanhf(0.7978845608028654f * (x + 0.044715f * x3)));
}

// ---------------- fp32 -> fp16 conversion ----------------
__global__ void f2h_kernel(const float* __restrict__ x, __half* __restrict__ y, int n) {
    int i = (blockIdx.x * blockDim.x + threadIdx.x) * 4;
    if (i < n) {
        float4 v = *(const float4*)(x + i);
        __half2* yo = (__half2*)(y + i);
        yo[0] = __floats2half2_rn(v.x, v.y);
        yo[1] = __floats2half2_rn(v.z, v.w);
    }
}

// ---------------- LayerNorm (fp32 out + fp16 out) ----------------
__global__ void ln_kernel(const float* __restrict__ x,
                          const float* __restrict__ w,
                          const float* __restrict__ b,
                          float* __restrict__ out,
                          __half* __restrict__ outh) {
    int row = blockIdx.x;
    int t = threadIdx.x;
    const float* xr = x + (size_t)row * H_DIM;
    float v[16];
    float s = 0.f;
    #pragma unroll
    for (int i = 0; i < 16; i++) { v[i] = xr[t + i * 256]; s += v[i]; }

    __shared__ float sh[8];
    __shared__ float s_mean, s_rstd;
    int lane = t & 31, wid = t >> 5;

    s = warpSum(s);
    if (lane == 0) sh[wid] = s;
    __syncthreads();
    if (t == 0) {
        float tot = 0.f;
        #pragma unroll
        for (int i = 0; i < 8; i++) tot += sh[i];
        s_mean = tot / (float)H_DIM;
    }
    __syncthreads();
    float m = s_mean;

    float vs = 0.f;
    #pragma unroll
    for (int i = 0; i < 16; i++) { float d = v[i] - m; vs += d * d; }
    vs = warpSum(vs);
    __syncthreads();
    if (lane == 0) sh[wid] = vs;
    __syncthreads();
    if (t == 0) {
        float tot = 0.f;
        #pragma unroll
        for (int i = 0; i < 8; i++) tot += sh[i];
        s_rstd = rsqrtf(tot / (float)H_DIM + EPS);
    }
    __syncthreads();
    float r = s_rstd;

    float* orow = out + (size_t)row * H_DIM;
    __half* hrow = outh + (size_t)row * H_DIM;
    #pragma unroll
    for (int i = 0; i < 16; i++) {
        int c = t + i * 256;
        float o = (v[i] - m) * r * w[c] + b[c];
        orow[c] = o;
        hrow[c] = __float2half_rn(o);
    }
}

// ---------------- RoPE (GLM dual rotary), in-place on qkv -------------------
__global__ void rope_kernel(float* __restrict__ qkv,
                            const float* __restrict__ cosc,
                            const float* __restrict__ sinc) {
    int s = blockIdx.x, h = blockIdx.y;
    float* base = qkv + (size_t)s * QKV3 + h * 384;
    __shared__ float buf[256];
    int t = threadIdx.x;
    buf[t] = base[t];
    __syncthreads();

    int isK  = (t >= 128) ? 128 : 0;
    int d    = t & 127;
    int half = d >> 6;
    int dd   = d & 63;

    int pos;
    if (half == 0) pos = (s < S_LEN - 1) ? s : (S_LEN - 2);
    else           pos = (s == S_LEN - 1) ? 1 : 0;

    float c  = cosc[pos * 64 + dd];
    float sn = sinc[pos * 64 + dd];

    int boff = isK + half * 64;
    float x   = buf[boff + dd];
    float rot = (dd < 32) ? -buf[boff + dd + 32] : buf[boff + dd - 32];
    base[t] = x * c + rot * sn;
}

// ---------------- fused attention (fp16 context out) ----------------
__global__ void attn_kernel(const float* __restrict__ qkv,
                            __half* __restrict__ ctx) {
    int q = blockIdx.x, h = blockIdx.y;
    int t = threadIdx.x;
    __shared__ float Qs[HD];
    __shared__ float P[S_LEN];
    __shared__ float sh[4];
    __shared__ float s_max, s_inv;

    const float scale = SCALING / COEFF;
    Qs[t] = qkv[(size_t)q * QKV3 + h * 384 + t] * scale;
    __syncthreads();

    const float* Kbase = qkv + h * 384 + 128;
    float lmax = -1e30f;
    for (int k = t; k < S_LEN; k += 128) {
        const float* Kr = Kbase + (size_t)k * QKV3;
        float acc = 0.f;
        #pragma unroll 8
        for (int d = 0; d < HD; d++) acc += Qs[d] * Kr[d];
        P[k] = acc;
        lmax = fmaxf(lmax, acc);
    }
    int lane = t & 31, wid = t >> 5;
    lmax = warpMax(lmax);
    if (lane == 0) sh[wid] = lmax;
    __syncthreads();
    if (t == 0) s_max = fmaxf(fmaxf(sh[0], sh[1]), fmaxf(sh[2], sh[3]));
    __syncthreads();
    float gmax = s_max;

    float lsum = 0.f;
    for (int k = t; k < S_LEN; k += 128) {
        float e = __expf(P[k] - gmax);
        P[k] = e;
        lsum += e;
    }
    lsum = warpSum(lsum);
    __syncthreads();
    if (lane == 0) sh[wid] = lsum;
    __syncthreads();
    if (t == 0) s_inv = 1.f / (sh[0] + sh[1] + sh[2] + sh[3]);
    __syncthreads();
    float inv = s_inv;

    const float* Vb = qkv + h * 384 + 256 + t;
    float acc = 0.f;
    #pragma unroll 8
    for (int k = 0; k < S_LEN; k++) acc += P[k] * Vb[(size_t)k * QKV3];
    ctx[(size_t)q * H_DIM + h * HD + t] = __float2half_rn(acc * inv);
}

// ============== HFMA2 GEMM: C[M,N] = A[M,K]*B[N,K]^T (fp16 in) ==============
// CTA 128x128, 256 thr, 8 warps (2m x 4n), thread tile 8x8.
// K packed in half2 pairs: acc2.lo sums even k, acc2.hi sums odd k.
// fp16 accumulation only within one 32-k tile, then flushed to fp32 accf.
// Smem rows: 32 halves (64B) + 16B pad = 80B stride -> conflict-free LDS.32.

#define BK 32                      // halves per k-tile
#define RSTB 80                    // smem row stride bytes
#define T_BYTES (128 * RSTB)       // 10240 per matrix tile
#define BUF_BYTES (2 * T_BYTES)    // 20480 per stage

__device__ __forceinline__ void cp_async16(uint32_t sa, const void* g) {
    asm volatile("cp.async.cg.shared.global [%0], [%1], 16;\n" :: "r"(sa), "l"(g));
}
__device__ __forceinline__ void cp_commit() {
    asm volatile("cp.async.commit_group;\n");
}
template <int N>
__device__ __forceinline__ void cp_wait() {
    asm volatile("cp.async.wait_group %0;\n" :: "n"(N));
}

// EPI: 0 = bias ; 1 = gelu(bias+acc) ; 2 = bias+acc + alpha*res
// OUTH: 1 -> __half out, 0 -> float out
template <int EPI, int OUTH>
__global__ void __launch_bounds__(256, 1)
gemm_h2(const __half* __restrict__ A, const __half* __restrict__ B,
        const float* __restrict__ bias, const float* __restrict__ res,
        float alpha, void* __restrict__ Cv, int M, int N, int K) {
    __shared__ __align__(16) char smem[2][BUF_BYTES];

    const int tid  = threadIdx.x;
    const int lane = tid & 31;
    const int wid  = tid >> 5;
    const int wm   = wid & 1;         // 0..1  -> 64-row slab
    const int wn   = wid >> 1;        // 0..3  -> 32-col slab
    const int tm   = lane & 7;        // 0..7
    const int tn   = lane >> 3;       // 0..3

    const int m0 = blockIdx.x * 128;
    const int n0 = blockIdx.y * 128;

    // gmem -> smem: 16B chunks (8 halves); row2 = tid>>2 (0..63), kc = tid&3
    const int row2 = tid >> 2;
    const int kc   = tid & 3;

    const __half* Ag = A + (size_t)(m0 + row2) * K + kc * 8;
    const __half* Bg = B + (size_t)(n0 + row2) * K + kc * 8;

    const uint32_t s0 = (uint32_t)__cvta_generic_to_shared(&smem[0][0]);

    __half2 acc2[8][8];
    float   accf[8][8];
    const __half2 h2z = __float2half2_rn(0.f);
    #pragma unroll
    for (int i = 0; i < 8; i++)
        #pragma unroll
        for (int j = 0; j < 8; j++) { acc2[i][j] = h2z; accf[i][j] = 0.f; }

    const int nk = K >> 5;

    auto issue = [&](int kt, int b) {
        uint32_t ab = s0 + (uint32_t)b * BUF_BYTES;
        uint32_t bb = ab + T_BYTES;
        const __half* ag = Ag + (size_t)kt * BK;
        const __half* bg = Bg + (size_t)kt * BK;
        #pragma unroll
        for (int i = 0; i < 2; i++) {
            cp_async16(ab + (uint32_t)(row2 + 64 * i) * RSTB + kc * 16,
                       ag + (size_t)(64 * i) * K);
            cp_async16(bb + (uint32_t)(row2 + 64 * i) * RSTB + kc * 16,
                       bg + (size_t)(64 * i) * K);
        }
        cp_commit();
    };

    issue(0, 0);

    const int arow = wm * 64 + tm;     // + 8*i
    const int brow = wn * 32 + tn;     // + 4*j

    for (int kt = 0; kt < nk; kt++) {
        if (kt + 1 < nk) { issue(kt + 1, (kt + 1) & 1); cp_wait<1>(); }
        else             cp_wait<0>();
        __syncthreads();

        const char* As = smem[kt & 1];
        const char* Bs = As + T_BYTES;

        #pragma unroll
        for (int kp = 0; kp < 16; kp++) {        // 16 k-pairs = 32 k
            __half2 a2[8], b2[8];
            #pragma unroll
            for (int i = 0; i < 8; i++)
                a2[i] = *(const __half2*)(As + (arow + 8 * i) * RSTB + kp * 4);
            #pragma unroll
            for (int j = 0; j < 8; j++)
                b2[j] = *(const __half2*)(Bs + (brow + 4 * j) * RSTB + kp * 4);
            #pragma unroll
            for (int i = 0; i < 8; i++)
                #pragma unroll
                for (int j = 0; j < 8; j++)
                    acc2[i][j] = __hfma2(a2[i], b2[j], acc2[i][j]);
        }

        // flush fp16 chunk sums into fp32 accumulators
        #pragma unroll
        for (int i = 0; i < 8; i++)
            #pragma unroll
            for (int j = 0; j < 8; j++) {
                float2 f = __half22float2(acc2[i][j]);
                accf[i][j] += f.x + f.y;
                acc2[i][j] = h2z;
            }
        __syncthreads();
    }

    // epilogue
    #pragma unroll
    for (int i = 0; i < 8; i++) {
        const int m = m0 + arow + 8 * i;
        const float* rrow = res + (size_t)m * N;
        #pragma unroll
        for (int j = 0; j < 8; j++) {
            const int n = n0 + brow + 4 * j;
            float v = accf[i][j] + bias[n];
            if (EPI == 1) v = gelu_tanh(v);
            if (EPI == 2) v += alpha * rrow[n];
            if (OUTH) ((__half*)Cv)[(size_t)m * N + n] = __float2half_rn(v);
            else      ((float*)Cv)[(size_t)m * N + n] = v;
        }
    }
}

// ---------------- launch ----------------------------------------------------
extern "C" void kernel_launch(void* const* d_in, const int* in_sizes, int n_in,
                              void* d_out, int out_size) {
    const float* hidden  = (const float*)d_in[0];
    const float* cosc    = (const float*)d_in[4];
    const float* sinc    = (const float*)d_in[5];
    const float* ln1_w   = (const float*)d_in[6];
    const float* ln1_b   = (const float*)d_in[7];
    const float* qkv_w   = (const float*)d_in[8];
    const float* qkv_b   = (const float*)d_in[9];
    const float* dense_w = (const float*)d_in[10];
    const float* dense_b = (const float*)d_in[11];
    const float* ln2_w   = (const float*)d_in[12];
    const float* ln2_b   = (const float*)d_in[13];
    const float* mlp_w1  = (const float*)d_in[14];
    const float* mlp_b1  = (const float*)d_in[15];
    const float* mlp_w2  = (const float*)d_in[16];
    const float* mlp_b2  = (const float*)d_in[17];
    float* out = (float*)d_out;

    float *res1, *qkvb, *hid, *res2;
    __half *res1h, *res2h, *ctxh, *acth, *qkv_wh, *dense_wh, *w1h, *w2h;
    cudaGetSymbolAddress((void**)&res1,  g_res1);
    cudaGetSymbolAddress((void**)&qkvb,  g_qkv);
    cudaGetSymbolAddress((void**)&hid,   g_hidden);
    cudaGetSymbolAddress((void**)&res2,  g_res2);
    cudaGetSymbolAddress((void**)&res1h, g_res1h);
    cudaGetSymbolAddress((void**)&res2h, g_res2h);
    cudaGetSymbolAddress((void**)&ctxh,  g_ctxh);
    cudaGetSymbolAddress((void**)&acth,  g_acth);
    cudaGetSymbolAddress((void**)&qkv_wh,   g_qkv_wh);
    cudaGetSymbolAddress((void**)&dense_wh, g_dense_wh);
    cudaGetSymbolAddress((void**)&w1h,      g_w1h);
    cudaGetSymbolAddress((void**)&w2h,      g_w2h);

    // 0. weight conversions fp32 -> fp16
    {
        int n;
        n = QKV3 * H_DIM;  f2h_kernel<<<n / 1024, 256>>>(qkv_w,   qkv_wh,   n);
        n = H_DIM * H_DIM; f2h_kernel<<<n / 1024, 256>>>(dense_w, dense_wh, n);
        n = INNER * H_DIM; f2h_kernel<<<n / 1024, 256>>>(mlp_w1,  w1h,      n);
        n = H_DIM * INNER; f2h_kernel<<<n / 1024, 256>>>(mlp_w2,  w2h,      n);
    }

    // 1. LN1
    ln_kernel<<<S_LEN, 256>>>(hidden, ln1_w, ln1_b, res1, res1h);

    // 2. QKV GEMM: [2048,4096] x [12288,4096]^T -> fp32 qkv
    {
        dim3 grid(S_LEN / 128, QKV3 / 128);
        gemm_h2<0,0><<<grid, 256>>>(res1h, qkv_wh, qkv_b, res1, 0.f,
                                    qkvb, S_LEN, QKV3, H_DIM);
    }

    // 3. RoPE
    {
        dim3 grid(S_LEN, NH);
        rope_kernel<<<grid, 256>>>(qkvb, cosc, sinc);
    }

    // 4. attention (fp16 ctx out)
    {
        dim3 grid(S_LEN, NH);
        attn_kernel<<<grid, 128>>>(qkvb, ctxh);
    }

    // 5. dense GEMM + alpha*residual
    {
        dim3 grid(S_LEN / 128, H_DIM / 128);
        gemm_h2<2,0><<<grid, 256>>>(ctxh, dense_wh, dense_b, res1, ALPHA,
                                    hid, S_LEN, H_DIM, H_DIM);
    }

    // 6. LN2
    ln_kernel<<<S_LEN, 256>>>(hid, ln2_w, ln2_b, res2, res2h);

    // 7. MLP up + gelu (fp16 out)
    {
        dim3 grid(S_LEN / 128, INNER / 128);
        gemm_h2<1,1><<<grid, 256>>>(res2h, w1h, mlp_b1, res2, 0.f,
                                    acth, S_LEN, INNER, H_DIM);
    }

    // 8. MLP down + alpha*residual -> output
    {
        dim3 grid(S_LEN / 128, H_DIM / 128);
        gemm_h2<2,0><<<grid, 256>>>(acth, w2h, mlp_b2, res2, ALPHA,
                                    out, S_LEN, H_DIM, INNER);
    }
}

// round 7
// speedup vs baseline: 1.0538x; 1.0027x over previous
#include <cuda_runtime.h>
#include <math.h>
#include <stdint.h>

#define S_LEN 2048
#define H_DIM 4096
#define NH 32
#define HD 128
#define INNER 16384
#define QKV3 12288   // 3*H

static constexpr float ALPHA   = 7.4833147735478827f;  // sqrt(56)
static constexpr float SCALING = 1.0f;                 // layer_id+1 = 1
static constexpr float COEFF   = 11.313708498984761f;  // sqrt(128)*1
static constexpr float EPS     = 1e-5f;

// ---------------- scratch (device globals; no allocations allowed) ----------
__device__ __align__(1024) float g_res1  [(size_t)S_LEN * H_DIM];
__device__ __align__(1024) float g_qkv   [(size_t)S_LEN * QKV3];
__device__ __align__(1024) float g_ctx   [(size_t)S_LEN * H_DIM];
__device__ __align__(1024) float g_hidden[(size_t)S_LEN * H_DIM];
__device__ __align__(1024) float g_res2  [(size_t)S_LEN * H_DIM];
__device__ __align__(1024) float g_act   [(size_t)S_LEN * INNER];

// ---------------- helpers ----------------
__device__ __forceinline__ float warpSum(float v) {
    #pragma unroll
    for (int o = 16; o > 0; o >>= 1) v += __shfl_xor_sync(0xffffffffu, v, o);
    return v;
}
__device__ __forceinline__ float warpMax(float v) {
    #pragma unroll
    for (int o = 16; o > 0; o >>= 1) v = fmaxf(v, __shfl_xor_sync(0xffffffffu, v, o));
    return v;
}
__device__ __forceinline__ float gelu_tanh(float x) {
    float x3 = x * x * x;
    return 0.5f * x * (1.f + tanhf(0.7978845608028654f * (x + 0.044715f * x3)));
}

// ---------------- LayerNorm ----------------
__global__ void ln_kernel(const float* __restrict__ x,
                          const float* __restrict__ w,
                          const float* __restrict__ b,
                          float* __restrict__ out) {
    int row = blockIdx.x;
    int t = threadIdx.x;
    const float* xr = x + (size_t)row * H_DIM;
    float v[16];
    float s = 0.f;
    #pragma unroll
    for (int i = 0; i < 16; i++) { v[i] = xr[t + i * 256]; s += v[i]; }

    __shared__ float sh[8];
    __shared__ float s_mean, s_rstd;
    int lane = t & 31, wid = t >> 5;

    s = warpSum(s);
    if (lane == 0) sh[wid] = s;
    __syncthreads();
    if (t == 0) {
        float tot = 0.f;
        #pragma unroll
        for (int i = 0; i < 8; i++) tot += sh[i];
        s_mean = tot / (float)H_DIM;
    }
    __syncthreads();
    float m = s_mean;

    float vs = 0.f;
    #pragma unroll
    for (int i = 0; i < 16; i++) { float d = v[i] - m; vs += d * d; }
    vs = warpSum(vs);
    __syncthreads();
    if (lane == 0) sh[wid] = vs;
    __syncthreads();
    if (t == 0) {
        float tot = 0.f;
        #pragma unroll
        for (int i = 0; i < 8; i++) tot += sh[i];
        s_rstd = rsqrtf(tot / (float)H_DIM + EPS);
    }
    __syncthreads();
    float r = s_rstd;

    float* orow = out + (size_t)row * H_DIM;
    #pragma unroll
    for (int i = 0; i < 16; i++) {
        int c = t + i * 256;
        orow[c] = (v[i] - m) * r * w[c] + b[c];
    }
}

// ---------------- RoPE (GLM dual rotary), in-place on qkv -------------------
__global__ void rope_kernel(float* __restrict__ qkv,
                            const float* __restrict__ cosc,
                            const float* __restrict__ sinc) {
    int s = blockIdx.x, h = blockIdx.y;
    float* base = qkv + (size_t)s * QKV3 + h * 384;
    __shared__ float buf[256];
    int t = threadIdx.x;
    buf[t] = base[t];
    __syncthreads();

    int isK  = (t >= 128) ? 128 : 0;
    int d    = t & 127;
    int half = d >> 6;
    int dd   = d & 63;

    int pos;
    if (half == 0) pos = (s < S_LEN - 1) ? s : (S_LEN - 2);
    else           pos = (s == S_LEN - 1) ? 1 : 0;

    float c  = cosc[pos * 64 + dd];
    float sn = sinc[pos * 64 + dd];

    int boff = isK + half * 64;
    float x   = buf[boff + dd];
    float rot = (dd < 32) ? -buf[boff + dd + 32] : buf[boff + dd - 32];
    base[t] = x * c + rot * sn;
}

// ---------------- fused attention ----------------
__global__ void attn_kernel(const float* __restrict__ qkv,
                            float* __restrict__ ctx) {
    int q = blockIdx.x, h = blockIdx.y;
    int t = threadIdx.x;
    __shared__ float Qs[HD];
    __shared__ float P[S_LEN];
    __shared__ float sh[4];
    __shared__ float s_max, s_inv;

    const float scale = SCALING / COEFF;
    Qs[t] = qkv[(size_t)q * QKV3 + h * 384 + t] * scale;
    __syncthreads();

    const float* Kbase = qkv + h * 384 + 128;
    float lmax = -1e30f;
    for (int k = t; k < S_LEN; k += 128) {
        const float* Kr = Kbase + (size_t)k * QKV3;
        float acc = 0.f;
        #pragma unroll 8
        for (int d = 0; d < HD; d++) acc += Qs[d] * Kr[d];
        P[k] = acc;
        lmax = fmaxf(lmax, acc);
    }
    int lane = t & 31, wid = t >> 5;
    lmax = warpMax(lmax);
    if (lane == 0) sh[wid] = lmax;
    __syncthreads();
    if (t == 0) s_max = fmaxf(fmaxf(sh[0], sh[1]), fmaxf(sh[2], sh[3]));
    __syncthreads();
    float gmax = s_max;

    float lsum = 0.f;
    for (int k = t; k < S_LEN; k += 128) {
        float e = __expf(P[k] - gmax);
        P[k] = e;
        lsum += e;
    }
    lsum = warpSum(lsum);
    __syncthreads();
    if (lane == 0) sh[wid] = lsum;
    __syncthreads();
    if (t == 0) s_inv = 1.f / (sh[0] + sh[1] + sh[2] + sh[3]);
    __syncthreads();
    float inv = s_inv;

    const float* Vb = qkv + h * 384 + 256 + t;
    float acc = 0.f;
    #pragma unroll 8
    for (int k = 0; k < S_LEN; k++) acc += P[k] * Vb[(size_t)k * QKV3];
    ctx[(size_t)q * H_DIM + h * HD + t] = acc * inv;
}

// ============ classic transposed-smem SGEMM: C = A[M,K]*B[N,K]^T ============
// CTA 128x128, BK=8, 256 threads, 8 warps (2m x 4n), warp 64x32, thread 8x8.
// Smem holds A,B transposed: As[k][m], Bs[k][n], stride 132 -> conflict-free
// STS (transpose store) and LDS.128 fragment loads on BOTH operands.
// Register-staged gmem double buffering, 2 CTAs/SM.

#define BKK 8
#define LSTR 132

// EPI: 0 = bias ; 1 = gelu(bias+acc) ; 2 = bias+acc + alpha*res
template <int EPI>
__global__ void __launch_bounds__(256, 2)
gemm_s(const float* __restrict__ A, const float* __restrict__ B,
       const float* __restrict__ bias, const float* __restrict__ res,
       float alpha, float* __restrict__ C, int M, int N, int K) {
    __shared__ float As[2][BKK][LSTR];
    __shared__ float Bs[2][BKK][LSTR];

    const int tid  = threadIdx.x;
    const int lane = tid & 31;
    const int wid  = tid >> 5;
    const int wm   = wid & 1;          // 0..1 -> 64-row slab
    const int wn   = wid >> 1;         // 0..3 -> 32-col slab

    const int m0 = blockIdx.x * 128;
    const int n0 = blockIdx.y * 128;

    const int am = wm * 64 + (lane & 7) * 4;     // + {0,32}
    const int bn = wn * 32 + (lane >> 3) * 4;    // + {0,16}

    // gmem load mapping: one float4 per thread per matrix per k-tile
    const int lrow = tid >> 1;         // 0..127
    const int lk4  = (tid & 1) * 4;    // 0 or 4

    const float* Ag = A + (size_t)(m0 + lrow) * K + lk4;
    const float* Bg = B + (size_t)(n0 + lrow) * K + lk4;

    float acc[8][8];
    #pragma unroll
    for (int i = 0; i < 8; i++)
        #pragma unroll
        for (int j = 0; j < 8; j++) acc[i][j] = 0.f;

    const int nk = K / BKK;

    // prologue: load + store tile 0
    float4 ra = *(const float4*)Ag;
    float4 rb = *(const float4*)Bg;
    As[0][lk4 + 0][lrow] = ra.x; As[0][lk4 + 1][lrow] = ra.y;
    As[0][lk4 + 2][lrow] = ra.z; As[0][lk4 + 3][lrow] = ra.w;
    Bs[0][lk4 + 0][lrow] = rb.x; Bs[0][lk4 + 1][lrow] = rb.y;
    Bs[0][lk4 + 2][lrow] = rb.z; Bs[0][lk4 + 3][lrow] = rb.w;
    __syncthreads();

    for (int kt = 0; kt < nk; kt++) {
        const int cur = kt & 1;
        const bool more = (kt + 1 < nk);
        if (more) {
            ra = *(const float4*)(Ag + (size_t)(kt + 1) * BKK);
            rb = *(const float4*)(Bg + (size_t)(kt + 1) * BKK);
        }

        #pragma unroll
        for (int k = 0; k < BKK; k++) {
            float4 a0 = *(const float4*)&As[cur][k][am];
            float4 a1 = *(const float4*)&As[cur][k][am + 32];
            float4 b0 = *(const float4*)&Bs[cur][k][bn];
            float4 b1 = *(const float4*)&Bs[cur][k][bn + 16];
            float av[8] = {a0.x, a0.y, a0.z, a0.w, a1.x, a1.y, a1.z, a1.w};
            float bv[8] = {b0.x, b0.y, b0.z, b0.w, b1.x, b1.y, b1.z, b1.w};
            #pragma unroll
            for (int i = 0; i < 8; i++)
                #pragma unroll
                for (int j = 0; j < 8; j++)
                    acc[i][j] = fmaf(av[i], bv[j], acc[i][j]);
        }

        if (more) {
            const int nxt = cur ^ 1;
            As[nxt][lk4 + 0][lrow] = ra.x; As[nxt][lk4 + 1][lrow] = ra.y;
            As[nxt][lk4 + 2][lrow] = ra.z; As[nxt][lk4 + 3][lrow] = ra.w;
            Bs[nxt][lk4 + 0][lrow] = rb.x; Bs[nxt][lk4 + 1][lrow] = rb.y;
            Bs[nxt][lk4 + 2][lrow] = rb.z; Bs[nxt][lk4 + 3][lrow] = rb.w;
        }
        __syncthreads();
    }

    // epilogue: rows m(i) = m0 + am + (i>>2)*32 + (i&3); cols bn+{0..3},{16..19}
    #pragma unroll
    for (int i = 0; i < 8; i++) {
        const int m = m0 + am + (i >> 2) * 32 + (i & 3);
        float* crow = C + (size_t)m * N + n0;
        const float* rrow = res + (size_t)m * N + n0;

        float v[8];
        #pragma unroll
        for (int j = 0; j < 8; j++) {
            const int n = bn + (j >> 2) * 16 + (j & 3);
            v[j] = acc[i][j] + bias[n0 + n];
            if (EPI == 1) v[j] = gelu_tanh(v[j]);
            if (EPI == 2) v[j] += alpha * rrow[n];
        }
        *(float4*)(crow + bn)      = make_float4(v[0], v[1], v[2], v[3]);
        *(float4*)(crow + bn + 16) = make_float4(v[4], v[5], v[6], v[7]);
    }
}

// ---------------- launch ----------------------------------------------------
extern "C" void kernel_launch(void* const* d_in, const int* in_sizes, int n_in,
                              void* d_out, int out_size) {
    const float* hidden  = (const float*)d_in[0];
    const float* cosc    = (const float*)d_in[4];
    const float* sinc    = (const float*)d_in[5];
    const float* ln1_w   = (const float*)d_in[6];
    const float* ln1_b   = (const float*)d_in[7];
    const float* qkv_w   = (const float*)d_in[8];
    const float* qkv_b   = (const float*)d_in[9];
    const float* dense_w = (const float*)d_in[10];
    const float* dense_b = (const float*)d_in[11];
    const float* ln2_w   = (const float*)d_in[12];
    const float* ln2_b   = (const float*)d_in[13];
    const float* mlp_w1  = (const float*)d_in[14];
    const float* mlp_b1  = (const float*)d_in[15];
    const float* mlp_w2  = (const float*)d_in[16];
    const float* mlp_b2  = (const float*)d_in[17];
    float* out = (float*)d_out;

    float *res1, *qkvb, *ctx, *hid, *res2, *act;
    cudaGetSymbolAddress((void**)&res1, g_res1);
    cudaGetSymbolAddress((void**)&qkvb, g_qkv);
    cudaGetSymbolAddress((void**)&ctx,  g_ctx);
    cudaGetSymbolAddress((void**)&hid,  g_hidden);
    cudaGetSymbolAddress((void**)&res2, g_res2);
    cudaGetSymbolAddress((void**)&act,  g_act);

    // 1. LN1
    ln_kernel<<<S_LEN, 256>>>(hidden, ln1_w, ln1_b, res1);

    // 2. QKV GEMM: [2048,4096] x [12288,4096]^T
    {
        dim3 grid(S_LEN / 128, QKV3 / 128);
        gemm_s<0><<<grid, 256>>>(res1, qkv_w, qkv_b, res1, 0.f,
                                 qkvb, S_LEN, QKV3, H_DIM);
    }

    // 3. RoPE
    {
        dim3 grid(S_LEN, NH);
        rope_kernel<<<grid, 256>>>(qkvb, cosc, sinc);
    }

    // 4. attention
    {
        dim3 grid(S_LEN, NH);
        attn_kernel<<<grid, 128>>>(qkvb, ctx);
    }

    // 5. dense GEMM + alpha*residual
    {
        dim3 grid(S_LEN / 128, H_DIM / 128);
        gemm_s<2><<<grid, 256>>>(ctx, dense_w, dense_b, res1, ALPHA,
                                 hid, S_LEN, H_DIM, H_DIM);
    }

    // 6. LN2
    ln_kernel<<<S_LEN, 256>>>(hid, ln2_w, ln2_b, res2);

    // 7. MLP up + gelu
    {
        dim3 grid(S_LEN / 128, INNER / 128);
        gemm_s<1><<<grid, 256>>>(res2, mlp_w1, mlp_b1, res2, 0.f,
                                 act, S_LEN, INNER, H_DIM);
    }

    // 8. MLP down + alpha*residual -> output
    {
        dim3 grid(S_LEN / 128, H_DIM / 128);
        gemm_s<2><<<grid, 256>>>(act, mlp_w2, mlp_b2, res2, ALPHA,
                                 out, S_LEN, H_DIM, INNER);
    }
}

// round 11
// speedup vs baseline: 14.8466x; 14.0888x over previous
#include <cuda_runtime.h>
#include <cuda_fp16.h>
#include <math.h>
#include <stdint.h>

#define S_LEN 2048
#define H_DIM 4096
#define NH 32
#define HD 128
#define INNER 16384
#define QKV3 12288   // 3*H

static constexpr float ALPHA   = 7.4833147735478827f;  // sqrt(56)
static constexpr float SCALING = 1.0f;                 // layer_id+1 = 1
static constexpr float COEFF   = 11.313708498984761f;  // sqrt(128)*1
static constexpr float EPS     = 1e-5f;

// ---------------- scratch (device globals; no allocations allowed) ----------
__device__ __align__(1024) float  g_res1  [(size_t)S_LEN * H_DIM];
__device__ __align__(1024) float  g_qkv   [(size_t)S_LEN * QKV3];
__device__ __align__(1024) float  g_hidden[(size_t)S_LEN * H_DIM];
__device__ __align__(1024) float  g_res2  [(size_t)S_LEN * H_DIM];

__device__ __align__(1024) __half g_res1h [(size_t)S_LEN * H_DIM];
__device__ __align__(1024) __half g_res2h [(size_t)S_LEN * H_DIM];
__device__ __align__(1024) __half g_ctxh  [(size_t)S_LEN * H_DIM];
__device__ __align__(1024) __half g_acth  [(size_t)S_LEN * INNER];

__device__ __align__(1024) __half g_qkv_wh  [(size_t)QKV3 * H_DIM];
__device__ __align__(1024) __half g_dense_wh[(size_t)H_DIM * H_DIM];
__device__ __align__(1024) __half g_w1h     [(size_t)INNER * H_DIM];
__device__ __align__(1024) __half g_w2h     [(size_t)H_DIM * INNER];

// ---------------- helpers ----------------
__device__ __forceinline__ float warpSum(float v) {
    #pragma unroll
    for (int o = 16; o > 0; o >>= 1) v += __shfl_xor_sync(0xffffffffu, v, o);
    return v;
}
__device__ __forceinline__ float gelu_tanh(float x) {
    float x3 = x * x * x;
    return 0.5f * x * (1.f + tanhf(0.7978845608028654f * (x + 0.044715f * x3)));
}

// ---------------- fp32 -> fp16 conversion ----------------
__global__ void f2h_kernel(const float* __restrict__ x, __half* __restrict__ y, int n) {
    int i = (blockIdx.x * blockDim.x + threadIdx.x) * 4;
    if (i < n) {
        float4 v = *(const float4*)(x + i);
        __half2* yo = (__half2*)(y + i);
        yo[0] = __floats2half2_rn(v.x, v.y);
        yo[1] = __floats2half2_rn(v.z, v.w);
    }
}

// ---------------- LayerNorm (fp32 out + fp16 out) ----------------
__global__ void ln_kernel(const float* __restrict__ x,
                          const float* __restrict__ w,
                          const float* __restrict__ b,
                          float* __restrict__ out,
                          __half* __restrict__ outh) {
    int row = blockIdx.x;
    int t = threadIdx.x;
    const float* xr = x + (size_t)row * H_DIM;
    float v[16];
    float s = 0.f;
    #pragma unroll
    for (int i = 0; i < 16; i++) { v[i] = xr[t + i * 256]; s += v[i]; }

    __shared__ float sh[8];
    __shared__ float s_mean, s_rstd;
    int lane = t & 31, wid = t >> 5;

    s = warpSum(s);
    if (lane == 0) sh[wid] = s;
    __syncthreads();
    if (t == 0) {
        float tot = 0.f;
        #pragma unroll
        for (int i = 0; i < 8; i++) tot += sh[i];
        s_mean = tot / (float)H_DIM;
    }
    __syncthreads();
    float m = s_mean;

    float vs = 0.f;
    #pragma unroll
    for (int i = 0; i < 16; i++) { float d = v[i] - m; vs += d * d; }
    vs = warpSum(vs);
    __syncthreads();
    if (lane == 0) sh[wid] = vs;
    __syncthreads();
    if (t == 0) {
        float tot = 0.f;
        #pragma unroll
        for (int i = 0; i < 8; i++) tot += sh[i];
        s_rstd = rsqrtf(tot / (float)H_DIM + EPS);
    }
    __syncthreads();
    float r = s_rstd;

    float* orow = out + (size_t)row * H_DIM;
    __half* hrow = outh + (size_t)row * H_DIM;
    #pragma unroll
    for (int i = 0; i < 16; i++) {
        int c = t + i * 256;
        float o = (v[i] - m) * r * w[c] + b[c];
        orow[c] = o;
        hrow[c] = __float2half_rn(o);
    }
}

// ---------------- RoPE (GLM dual rotary), in-place on qkv -------------------
__global__ void rope_kernel(float* __restrict__ qkv,
                            const float* __restrict__ cosc,
                            const float* __restrict__ sinc) {
    int s = blockIdx.x, h = blockIdx.y;
    float* base = qkv + (size_t)s * QKV3 + h * 384;
    __shared__ float buf[256];
    int t = threadIdx.x;
    buf[t] = base[t];
    __syncthreads();

    int isK  = (t >= 128) ? 128 : 0;
    int d    = t & 127;
    int half = d >> 6;
    int dd   = d & 63;

    int pos;
    if (half == 0) pos = (s < S_LEN - 1) ? s : (S_LEN - 2);
    else           pos = (s == S_LEN - 1) ? 1 : 0;

    float c  = cosc[pos * 64 + dd];
    float sn = sinc[pos * 64 + dd];

    int boff = isK + half * 64;
    float x   = buf[boff + dd];
    float rot = (dd < 32) ? -buf[boff + dd + 32] : buf[boff + dd - 32];
    base[t] = x * c + rot * sn;
}

// ============== flash-tiled attention: 64q x 64k tiles, fp32 ================
// grid (S/64, NH), 256 threads as 16(ty:q) x 16(tx:k|d).
// smem: QT[128][68] KT[128][68] transposed, Vs[64][132], Ps[64][68].
// Thread owns q rows 4ty+0..3 in BOTH phases -> softmax state in registers.

#define QTP 68
#define VSP 132
#define PSP 68
#define ATN_SMEM ((128*QTP + 128*QTP + 64*VSP + 64*PSP) * 4)

__global__ void __launch_bounds__(256, 1)
fattn_kernel(const float* __restrict__ qkv, __half* __restrict__ ctx) {
    extern __shared__ float sm[];
    float* QT = sm;                    // [128][QTP]
    float* KT = QT + 128 * QTP;        // [128][QTP]
    float* Vs = KT + 128 * QTP;        // [64][VSP]
    float* Ps = Vs + 64 * VSP;         // [64][PSP]

    const int tid = threadIdx.x;
    const int tx = tid & 15;
    const int ty = tid >> 4;
    const int q0 = blockIdx.x * 64;
    const int h  = blockIdx.y;

    const float scale = SCALING / COEFF;

    // load Q tile transposed (scaled)
    {
        const int r  = tid >> 2;
        const int cc = (tid & 3) * 4;
        const float* qg = qkv + (size_t)(q0 + r) * QKV3 + h * 384;
        #pragma unroll
        for (int i = 0; i < 8; i++) {
            int d = cc + 16 * i;
            float4 v = *(const float4*)(qg + d);
            QT[(d + 0) * QTP + r] = v.x * scale;
            QT[(d + 1) * QTP + r] = v.y * scale;
            QT[(d + 2) * QTP + r] = v.z * scale;
            QT[(d + 3) * QTP + r] = v.w * scale;
        }
    }

    float m_old[4], l_sum[4];
    float o_acc[4][8];
    #pragma unroll
    for (int i = 0; i < 4; i++) {
        m_old[i] = -1e30f; l_sum[i] = 0.f;
        #pragma unroll
        for (int j = 0; j < 8; j++) o_acc[i][j] = 0.f;
    }
    __syncthreads();

    for (int kt = 0; kt < S_LEN / 64; kt++) {
        const int kbase = kt * 64;
        // load K tile (transposed) + V tile (row-major), coalesced
        {
            const int r  = tid >> 2;
            const int cc = (tid & 3) * 4;
            const float* kg = qkv + (size_t)(kbase + r) * QKV3 + h * 384 + 128;
            const float* vg = kg + 128;
            #pragma unroll
            for (int i = 0; i < 8; i++) {
                int d = cc + 16 * i;
                float4 kv = *(const float4*)(kg + d);
                KT[(d + 0) * QTP + r] = kv.x;
                KT[(d + 1) * QTP + r] = kv.y;
                KT[(d + 2) * QTP + r] = kv.z;
                KT[(d + 3) * QTP + r] = kv.w;
                *(float4*)(Vs + r * VSP + d) = *(const float4*)(vg + d);
            }
        }
        __syncthreads();

        // S tile: q = 4ty+i, k = 4tx+j
        float s[4][4] = {};
        #pragma unroll 16
        for (int d = 0; d < 128; d++) {
            float4 a = *(const float4*)(QT + d * QTP + 4 * ty);
            float4 b = *(const float4*)(KT + d * QTP + 4 * tx);
            float av[4] = {a.x, a.y, a.z, a.w};
            float bv[4] = {b.x, b.y, b.z, b.w};
            #pragma unroll
            for (int i = 0; i < 4; i++)
                #pragma unroll
                for (int j = 0; j < 4; j++)
                    s[i][j] = fmaf(av[i], bv[j], s[i][j]);
        }

        // online softmax (row reductions across tx group = 16-lane segment)
        #pragma unroll
        for (int i = 0; i < 4; i++) {
            float mt = fmaxf(fmaxf(s[i][0], s[i][1]), fmaxf(s[i][2], s[i][3]));
            #pragma unroll
            for (int o = 8; o > 0; o >>= 1)
                mt = fmaxf(mt, __shfl_xor_sync(0xffffffffu, mt, o, 16));
            float mn = fmaxf(m_old[i], mt);
            float f  = __expf(m_old[i] - mn);
            m_old[i] = mn;
            float r = 0.f;
            #pragma unroll
            for (int j = 0; j < 4; j++) { s[i][j] = __expf(s[i][j] - mn); r += s[i][j]; }
            #pragma unroll
            for (int o = 8; o > 0; o >>= 1)
                r += __shfl_xor_sync(0xffffffffu, r, o, 16);
            l_sum[i] = l_sum[i] * f + r;
            #pragma unroll
            for (int j = 0; j < 8; j++) o_acc[i][j] *= f;
            *(float4*)(Ps + (4 * ty + i) * PSP + 4 * tx) =
                make_float4(s[i][0], s[i][1], s[i][2], s[i][3]);
        }
        __syncthreads();

        // O += P @ V : thread owns q rows 4ty+i, d cols {4tx..+3, 64+4tx..+3}
        #pragma unroll 8
        for (int k = 0; k < 64; k++) {
            float p[4];
            #pragma unroll
            for (int i = 0; i < 4; i++) p[i] = Ps[(4 * ty + i) * PSP + k];
            float4 v0 = *(const float4*)(Vs + k * VSP + 4 * tx);
            float4 v1 = *(const float4*)(Vs + k * VSP + 64 + 4 * tx);
            float vv[8] = {v0.x, v0.y, v0.z, v0.w, v1.x, v1.y, v1.z, v1.w};
            #pragma unroll
            for (int i = 0; i < 4; i++)
                #pragma unroll
                for (int j = 0; j < 8; j++)
                    o_acc[i][j] = fmaf(p[i], vv[j], o_acc[i][j]);
        }
        __syncthreads();
    }

    // epilogue: normalize and store fp16 ctx
    #pragma unroll
    for (int i = 0; i < 4; i++) {
        float inv = 1.f / l_sum[i];
        __half* crow = ctx + (size_t)(q0 + 4 * ty + i) * H_DIM + h * HD;
        __half2 h0 = __floats2half2_rn(o_acc[i][0] * inv, o_acc[i][1] * inv);
        __half2 h1 = __floats2half2_rn(o_acc[i][2] * inv, o_acc[i][3] * inv);
        __half2 h2 = __floats2half2_rn(o_acc[i][4] * inv, o_acc[i][5] * inv);
        __half2 h3 = __floats2half2_rn(o_acc[i][6] * inv, o_acc[i][7] * inv);
        *(__half2*)(crow + 4 * tx)      = h0;
        *(__half2*)(crow + 4 * tx + 2)  = h1;
        *(__half2*)(crow + 64 + 4 * tx)     = h2;
        *(__half2*)(crow + 64 + 4 * tx + 2) = h3;
    }
}

// ============== fp16 HMMA GEMM (R4, best measured): C = A*B^T ===============
#define BK 32
#define AST 80
#define A_SBYTES (128 * AST)
#define B_SBYTES (256 * AST)
#define BUF_SBYTES (A_SBYTES + B_SBYTES)
#define NBUF 3
#define GEMM_SMEM_BYTES (NBUF * BUF_SBYTES)

__device__ __forceinline__ void cp_async16(uint32_t sa, const void* g) {
    asm volatile("cp.async.cg.shared.global [%0], [%1], 16;\n" :: "r"(sa), "l"(g));
}
__device__ __forceinline__ void cp_commit() {
    asm volatile("cp.async.commit_group;\n");
}
template <int N>
__device__ __forceinline__ void cp_wait() {
    asm volatile("cp.async.wait_group %0;\n" :: "n"(N));
}

__device__ __forceinline__ void mma_f16(float& c0, float& c1, float& c2, float& c3,
                                        uint32_t a0, uint32_t a1, uint32_t a2, uint32_t a3,
                                        uint32_t b0, uint32_t b1) {
    asm volatile(
        "mma.sync.aligned.m16n8k16.row.col.f32.f16.f16.f32 "
        "{%0,%1,%2,%3}, {%4,%5,%6,%7}, {%8,%9}, {%0,%1,%2,%3};\n"
        : "+f"(c0), "+f"(c1), "+f"(c2), "+f"(c3)
        : "r"(a0), "r"(a1), "r"(a2), "r"(a3), "r"(b0), "r"(b1));
}

template <int EPI, int OUTH>
__global__ void __launch_bounds__(256, 1)
gemm_h(const __half* __restrict__ A, const __half* __restrict__ B,
       const float* __restrict__ bias, const float* __restrict__ res,
       float alpha, void* __restrict__ Cv, int M, int N, int K) {
    extern __shared__ char smem[];

    const int tid  = threadIdx.x;
    const int lane = tid & 31;
    const int wid  = tid >> 5;
    const int wm   = wid & 1;
    const int wn   = wid >> 1;
    const int g    = lane >> 2;
    const int c    = lane & 3;

    const int m0 = blockIdx.x * 128;
    const int n0 = blockIdx.y * 256;

    const uint32_t sbase = (uint32_t)__cvta_generic_to_shared(smem);
    const int row4 = tid >> 2;
    const int kc   = tid & 3;

    float acc[4][8][4];
    #pragma unroll
    for (int i = 0; i < 4; i++)
        #pragma unroll
        for (int j = 0; j < 8; j++)
            #pragma unroll
            for (int q = 0; q < 4; q++) acc[i][j][q] = 0.f;

    const int nk = K >> 5;

    auto issue = [&](int kt, int b) {
        uint32_t ab = sbase + (uint32_t)b * BUF_SBYTES;
        uint32_t bb = ab + A_SBYTES;
        const __half* ag = A + (size_t)(m0 + row4) * K + kt * BK + kc * 8;
        const __half* bg = B + (size_t)(n0 + row4) * K + kt * BK + kc * 8;
        #pragma unroll
        for (int i = 0; i < 2; i++)
            cp_async16(ab + (uint32_t)(row4 + 64 * i) * AST + kc * 16,
                       ag + (size_t)(64 * i) * K);
        #pragma unroll
        for (int i = 0; i < 4; i++)
            cp_async16(bb + (uint32_t)(row4 + 64 * i) * AST + kc * 16,
                       bg + (size_t)(64 * i) * K);
        cp_commit();
    };

    issue(0, 0);
    issue(1, 1);

    for (int kt = 0; kt < nk; kt++) {
        const int b = kt % NBUF;
        if (kt + 2 < nk) { issue(kt + 2, (kt + 2) % NBUF); cp_wait<2>(); }
        else if (kt + 1 < nk) cp_wait<1>();
        else cp_wait<0>();
        __syncthreads();

        const char* As = smem + (size_t)b * BUF_SBYTES;
        const char* Bs = As + A_SBYTES;

        #pragma unroll
        for (int ks = 0; ks < 2; ks++) {
            const int kb = ks * 32;
            uint32_t af[4][4];
            uint32_t bf[8][2];
            #pragma unroll
            for (int mt = 0; mt < 4; mt++) {
                int r = wm * 64 + mt * 16 + g;
                af[mt][0] = *(const uint32_t*)(As + r * AST + kb + c * 4);
                af[mt][1] = *(const uint32_t*)(As + (r + 8) * AST + kb + c * 4);
                af[mt][2] = *(const uint32_t*)(As + r * AST + kb + 16 + c * 4);
                af[mt][3] = *(const uint32_t*)(As + (r + 8) * AST + kb + 16 + c * 4);
            }
            #pragma unroll
            for (int nt = 0; nt < 8; nt++) {
                int r = wn * 64 + nt * 8 + g;
                bf[nt][0] = *(const uint32_t*)(Bs + r * AST + kb + c * 4);
                bf[nt][1] = *(const uint32_t*)(Bs + r * AST + kb + 16 + c * 4);
            }
            #pragma unroll
            for (int mt = 0; mt < 4; mt++)
                #pragma unroll
                for (int nt = 0; nt < 8; nt++)
                    mma_f16(acc[mt][nt][0], acc[mt][nt][1],
                            acc[mt][nt][2], acc[mt][nt][3],
                            af[mt][0], af[mt][1], af[mt][2], af[mt][3],
                            bf[nt][0], bf[nt][1]);
        }
        __syncthreads();
    }

    #pragma unroll
    for (int mt = 0; mt < 4; mt++) {
        int r0 = m0 + wm * 64 + mt * 16 + g;
        int r1 = r0 + 8;
        #pragma unroll
        for (int nt = 0; nt < 8; nt++) {
            int col = n0 + wn * 64 + nt * 8 + 2 * c;
            float b0v = bias[col], b1v = bias[col + 1];

            float v0 = acc[mt][nt][0] + b0v;
            float v1 = acc[mt][nt][1] + b1v;
            float v2 = acc[mt][nt][2] + b0v;
            float v3 = acc[mt][nt][3] + b1v;
            if (EPI == 1) {
                v0 = gelu_tanh(v0); v1 = gelu_tanh(v1);
                v2 = gelu_tanh(v2); v3 = gelu_tanh(v3);
            }
            if (EPI == 2) {
                const float* rr0 = res + (size_t)r0 * N + col;
                const float* rr1 = res + (size_t)r1 * N + col;
                v0 += alpha * rr0[0]; v1 += alpha * rr0[1];
                v2 += alpha * rr1[0]; v3 += alpha * rr1[1];
            }
            if (OUTH) {
                __half* C = (__half*)Cv;
                *(__half2*)(C + (size_t)r0 * N + col) = __floats2half2_rn(v0, v1);
                *(__half2*)(C + (size_t)r1 * N + col) = __floats2half2_rn(v2, v3);
            } else {
                float* C = (float*)Cv;
                *(float2*)(C + (size_t)r0 * N + col) = make_float2(v0, v1);
                *(float2*)(C + (size_t)r1 * N + col) = make_float2(v2, v3);
            }
        }
    }
}

// ---------------- launch ----------------------------------------------------
extern "C" void kernel_launch(void* const* d_in, const int* in_sizes, int n_in,
                              void* d_out, int out_size) {
    const float* hidden  = (const float*)d_in[0];
    const float* cosc    = (const float*)d_in[4];
    const float* sinc    = (const float*)d_in[5];
    const float* ln1_w   = (const float*)d_in[6];
    const float* ln1_b   = (const float*)d_in[7];
    const float* qkv_w   = (const float*)d_in[8];
    const float* qkv_b   = (const float*)d_in[9];
    const float* dense_w = (const float*)d_in[10];
    const float* dense_b = (const float*)d_in[11];
    const float* ln2_w   = (const float*)d_in[12];
    const float* ln2_b   = (const float*)d_in[13];
    const float* mlp_w1  = (const float*)d_in[14];
    const float* mlp_b1  = (const float*)d_in[15];
    const float* mlp_w2  = (const float*)d_in[16];
    const float* mlp_b2  = (const float*)d_in[17];
    float* out = (float*)d_out;

    float *res1, *qkvb, *hid, *res2;
    __half *res1h, *res2h, *ctxh, *acth, *qkv_wh, *dense_wh, *w1h, *w2h;
    cudaGetSymbolAddress((void**)&res1,  g_res1);
    cudaGetSymbolAddress((void**)&qkvb,  g_qkv);
    cudaGetSymbolAddress((void**)&hid,   g_hidden);
    cudaGetSymbolAddress((void**)&res2,  g_res2);
    cudaGetSymbolAddress((void**)&res1h, g_res1h);
    cudaGetSymbolAddress((void**)&res2h, g_res2h);
    cudaGetSymbolAddress((void**)&ctxh,  g_ctxh);
    cudaGetSymbolAddress((void**)&acth,  g_acth);
    cudaGetSymbolAddress((void**)&qkv_wh,   g_qkv_wh);
    cudaGetSymbolAddress((void**)&dense_wh, g_dense_wh);
    cudaGetSymbolAddress((void**)&w1h,      g_w1h);
    cudaGetSymbolAddress((void**)&w2h,      g_w2h);

    cudaFuncSetAttribute(gemm_h<0,0>, cudaFuncAttributeMaxDynamicSharedMemorySize, GEMM_SMEM_BYTES);
    cudaFuncSetAttribute(gemm_h<1,1>, cudaFuncAttributeMaxDynamicSharedMemorySize, GEMM_SMEM_BYTES);
    cudaFuncSetAttribute(gemm_h<2,0>, cudaFuncAttributeMaxDynamicSharedMemorySize, GEMM_SMEM_BYTES);
    cudaFuncSetAttribute(fattn_kernel, cudaFuncAttributeMaxDynamicSharedMemorySize, ATN_SMEM);

    // 0. weight conversions fp32 -> fp16
    {
        int n;
        n = QKV3 * H_DIM;  f2h_kernel<<<n / 1024, 256>>>(qkv_w,   qkv_wh,   n);
        n = H_DIM * H_DIM; f2h_kernel<<<n / 1024, 256>>>(dense_w, dense_wh, n);
        n = INNER * H_DIM; f2h_kernel<<<n / 1024, 256>>>(mlp_w1,  w1h,      n);
        n = H_DIM * INNER; f2h_kernel<<<n / 1024, 256>>>(mlp_w2,  w2h,      n);
    }

    // 1. LN1
    ln_kernel<<<S_LEN, 256>>>(hidden, ln1_w, ln1_b, res1, res1h);

    // 2. QKV GEMM -> fp32 qkv
    {
        dim3 grid(S_LEN / 128, QKV3 / 256);
        gemm_h<0,0><<<grid, 256, GEMM_SMEM_BYTES>>>(res1h, qkv_wh, qkv_b, res1, 0.f,
                                                    qkvb, S_LEN, QKV3, H_DIM);
    }

    // 3. RoPE
    {
        dim3 grid(S_LEN, NH);
        rope_kernel<<<grid, 256>>>(qkvb, cosc, sinc);
    }

    // 4. flash attention (fp16 ctx out)
    {
        dim3 grid(S_LEN / 64, NH);
        fattn_kernel<<<grid, 256, ATN_SMEM>>>(qkvb, ctxh);
    }

    // 5. dense GEMM + alpha*residual
    {
        dim3 grid(S_LEN / 128, H_DIM / 256);
        gemm_h<2,0><<<grid, 256, GEMM_SMEM_BYTES>>>(ctxh, dense_wh, dense_b, res1, ALPHA,
                                                    hid, S_LEN, H_DIM, H_DIM);
    }

    // 6. LN2
    ln_kernel<<<S_LEN, 256>>>(hid, ln2_w, ln2_b, res2, res2h);

    // 7. MLP up + gelu (fp16 out)
    {
        dim3 grid(S_LEN / 128, INNER / 256);
        gemm_h<1,1><<<grid, 256, GEMM_SMEM_BYTES>>>(res2h, w1h, mlp_b1, res2, 0.f,
                                                    acth, S_LEN, INNER, H_DIM);
    }

    // 8. MLP down + alpha*residual -> output
    {
        dim3 grid(S_LEN / 128, H_DIM / 256);
        gemm_h<2,0><<<grid, 256, GEMM_SMEM_BYTES>>>(acth, w2h, mlp_b2, res2, ALPHA,
                                                    out, S_LEN, H_DIM, INNER);
    }
}

// round 12
// speedup vs baseline: 21.5303x; 1.4502x over previous
#include <cuda_runtime.h>
#include <cuda_fp16.h>
#include <math.h>
#include <stdint.h>

#define S_LEN 2048
#define H_DIM 4096
#define NH 32
#define HD 128
#define INNER 16384
#define QKV3 12288   // 3*H

static constexpr float ALPHA   = 7.4833147735478827f;  // sqrt(56)
static constexpr float SCALING = 1.0f;                 // layer_id+1 = 1
static constexpr float COEFF   = 11.313708498984761f;  // sqrt(128)*1
static constexpr float EPS     = 1e-5f;

// ---------------- scratch (device globals; no allocations allowed) ----------
__device__ __align__(1024) float  g_res1  [(size_t)S_LEN * H_DIM];
__device__ __align__(1024) float  g_hidden[(size_t)S_LEN * H_DIM];
__device__ __align__(1024) float  g_res2  [(size_t)S_LEN * H_DIM];

__device__ __align__(1024) __half g_qkvh  [(size_t)S_LEN * QKV3];
__device__ __align__(1024) __half g_res1h [(size_t)S_LEN * H_DIM];
__device__ __align__(1024) __half g_res2h [(size_t)S_LEN * H_DIM];
__device__ __align__(1024) __half g_ctxh  [(size_t)S_LEN * H_DIM];
__device__ __align__(1024) __half g_acth  [(size_t)S_LEN * INNER];

__device__ __align__(1024) __half g_qkv_wh  [(size_t)QKV3 * H_DIM];
__device__ __align__(1024) __half g_dense_wh[(size_t)H_DIM * H_DIM];
__device__ __align__(1024) __half g_w1h     [(size_t)INNER * H_DIM];
__device__ __align__(1024) __half g_w2h     [(size_t)H_DIM * INNER];

// ---------------- helpers ----------------
__device__ __forceinline__ float warpSum(float v) {
    #pragma unroll
    for (int o = 16; o > 0; o >>= 1) v += __shfl_xor_sync(0xffffffffu, v, o);
    return v;
}
__device__ __forceinline__ float gelu_tanh(float x) {
    float x3 = x * x * x;
    return 0.5f * x * (1.f + tanhf(0.7978845608028654f * (x + 0.044715f * x3)));
}

__device__ __forceinline__ void cp_async16(uint32_t sa, const void* g) {
    asm volatile("cp.async.cg.shared.global [%0], [%1], 16;\n" :: "r"(sa), "l"(g));
}
__device__ __forceinline__ void cp_commit() {
    asm volatile("cp.async.commit_group;\n");
}
template <int N>
__device__ __forceinline__ void cp_wait() {
    asm volatile("cp.async.wait_group %0;\n" :: "n"(N));
}

__device__ __forceinline__ void mma_f16(float& c0, float& c1, float& c2, float& c3,
                                        uint32_t a0, uint32_t a1, uint32_t a2, uint32_t a3,
                                        uint32_t b0, uint32_t b1) {
    asm volatile(
        "mma.sync.aligned.m16n8k16.row.col.f32.f16.f16.f32 "
        "{%0,%1,%2,%3}, {%4,%5,%6,%7}, {%8,%9}, {%0,%1,%2,%3};\n"
        : "+f"(c0), "+f"(c1), "+f"(c2), "+f"(c3)
        : "r"(a0), "r"(a1), "r"(a2), "r"(a3), "r"(b0), "r"(b1));
}

// ---------------- fp32 -> fp16 conversion ----------------
__global__ void f2h_kernel(const float* __restrict__ x, __half* __restrict__ y, int n) {
    int i = (blockIdx.x * blockDim.x + threadIdx.x) * 4;
    if (i < n) {
        float4 v = *(const float4*)(x + i);
        __half2* yo = (__half2*)(y + i);
        yo[0] = __floats2half2_rn(v.x, v.y);
        yo[1] = __floats2half2_rn(v.z, v.w);
    }
}

// ---------------- LayerNorm (fp32 out + fp16 out) ----------------
__global__ void ln_kernel(const float* __restrict__ x,
                          const float* __restrict__ w,
                          const float* __restrict__ b,
                          float* __restrict__ out,
                          __half* __restrict__ outh) {
    int row = blockIdx.x;
    int t = threadIdx.x;
    const float* xr = x + (size_t)row * H_DIM;
    float v[16];
    float s = 0.f;
    #pragma unroll
    for (int i = 0; i < 16; i++) { v[i] = xr[t + i * 256]; s += v[i]; }

    __shared__ float sh[8];
    __shared__ float s_mean, s_rstd;
    int lane = t & 31, wid = t >> 5;

    s = warpSum(s);
    if (lane == 0) sh[wid] = s;
    __syncthreads();
    if (t == 0) {
        float tot = 0.f;
        #pragma unroll
        for (int i = 0; i < 8; i++) tot += sh[i];
        s_mean = tot / (float)H_DIM;
    }
    __syncthreads();
    float m = s_mean;

    float vs = 0.f;
    #pragma unroll
    for (int i = 0; i < 16; i++) { float d = v[i] - m; vs += d * d; }
    vs = warpSum(vs);
    __syncthreads();
    if (lane == 0) sh[wid] = vs;
    __syncthreads();
    if (t == 0) {
        float tot = 0.f;
        #pragma unroll
        for (int i = 0; i < 8; i++) tot += sh[i];
        s_rstd = rsqrtf(tot / (float)H_DIM + EPS);
    }
    __syncthreads();
    float r = s_rstd;

    float* orow = out + (size_t)row * H_DIM;
    __half* hrow = outh + (size_t)row * H_DIM;
    #pragma unroll
    for (int i = 0; i < 16; i++) {
        int c = t + i * 256;
        float o = (v[i] - m) * r * w[c] + b[c];
        orow[c] = o;
        hrow[c] = __float2half_rn(o);
    }
}

// ---------------- RoPE (GLM dual rotary), fp16 in-place on qkvh -------------
__global__ void rope_h_kernel(__half* __restrict__ qkv,
                              const float* __restrict__ cosc,
                              const float* __restrict__ sinc) {
    int s = blockIdx.x, h = blockIdx.y;
    __half* base = qkv + (size_t)s * QKV3 + h * 384;
    __shared__ float buf[256];
    int t = threadIdx.x;
    buf[t] = __half2float(base[t]);
    __syncthreads();

    int isK  = (t >= 128) ? 128 : 0;
    int d    = t & 127;
    int half = d >> 6;
    int dd   = d & 63;

    int pos;
    if (half == 0) pos = (s < S_LEN - 1) ? s : (S_LEN - 2);
    else           pos = (s == S_LEN - 1) ? 1 : 0;

    float c  = cosc[pos * 64 + dd];
    float sn = sinc[pos * 64 + dd];

    int boff = isK + half * 64;
    float x   = buf[boff + dd];
    float rot = (dd < 32) ? -buf[boff + dd + 32] : buf[boff + dd - 32];
    base[t] = __float2half_rn(x * c + rot * sn);
}

// ============== HMMA flash attention: 128q CTA, 64-key tiles ================
// 8 warps, warp owns 16 q rows. K,V fp16 row-major in smem (272B stride ->
// conflict-free fragment LDS). QK b-frags plain LDS (R4-proven pattern),
// PV b-frags via ldmatrix.x2.trans. Online softmax, exp via ex2.approx.f16x2.

#define KVSTR 272
#define TILE_B (64 * KVSTR)          // 17408
#define ATTN_SMEM (2 * 2 * TILE_B)   // 69632

__global__ void __launch_bounds__(256, 1)
fattn_mma(const __half* __restrict__ qkv, __half* __restrict__ ctx) {
    extern __shared__ char smem[];
    const uint32_t sbase = (uint32_t)__cvta_generic_to_shared(smem);
    const int tid  = threadIdx.x;
    const int lane = tid & 31;
    const int wid  = tid >> 5;
    const int g    = lane >> 2;
    const int c    = lane & 3;
    const int qb   = blockIdx.x * 128 + wid * 16;
    const int h    = blockIdx.y;

    // Q fragments (held in registers for all K tiles)
    uint32_t qf[8][4];
    {
        const __half* q0 = qkv + (size_t)(qb + g) * QKV3 + h * 384;
        const __half* q8 = q0 + (size_t)8 * QKV3;
        #pragma unroll
        for (int kc = 0; kc < 8; kc++) {
            qf[kc][0] = *(const uint32_t*)(q0 + kc * 16 + 2 * c);
            qf[kc][1] = *(const uint32_t*)(q8 + kc * 16 + 2 * c);
            qf[kc][2] = *(const uint32_t*)(q0 + kc * 16 + 2 * c + 8);
            qf[kc][3] = *(const uint32_t*)(q8 + kc * 16 + 2 * c + 8);
        }
    }

    float oacc[16][4];
    #pragma unroll
    for (int dn = 0; dn < 16; dn++)
        #pragma unroll
        for (int q = 0; q < 4; q++) oacc[dn][q] = 0.f;
    float m0 = -1e30f, m1 = -1e30f, l0 = 0.f, l1 = 0.f;

    auto load_tile = [&](int kt, int b) {
        uint32_t kb = sbase + (uint32_t)b * (2 * TILE_B);
        uint32_t vb = kb + TILE_B;
        const int kbase = kt * 64;
        #pragma unroll
        for (int i = 0; i < 4; i++) {
            int id = tid + 256 * i;
            int row = id >> 4, ch = id & 15;
            const __half* src = qkv + (size_t)(kbase + row) * QKV3 + h * 384 + 128 + ch * 8;
            cp_async16(kb + (uint32_t)row * KVSTR + ch * 16, src);
            cp_async16(vb + (uint32_t)row * KVSTR + ch * 16, src + 128);
        }
        cp_commit();
    };

    load_tile(0, 0);
    const float C1 = 0.12752697f;   // log2(e) * SCALING / COEFF

    for (int kt = 0; kt < S_LEN / 64; kt++) {
        const int b = kt & 1;
        if (kt + 1 < S_LEN / 64) { load_tile(kt + 1, b ^ 1); cp_wait<1>(); }
        else                     cp_wait<0>();
        __syncthreads();

        const char* Kc = smem + (size_t)b * (2 * TILE_B);
        const uint32_t vbase = sbase + (uint32_t)b * (2 * TILE_B) + TILE_B;

        // S = Q K^T  (8 n-tiles of 8 keys)
        float sacc[8][4];
        #pragma unroll
        for (int j = 0; j < 8; j++) {
            sacc[j][0] = sacc[j][1] = sacc[j][2] = sacc[j][3] = 0.f;
            #pragma unroll
            for (int kc = 0; kc < 8; kc++) {
                const char* kp = Kc + (j * 8 + g) * KVSTR + kc * 32 + 4 * c;
                uint32_t b0 = *(const uint32_t*)(kp);
                uint32_t b1 = *(const uint32_t*)(kp + 16);
                mma_f16(sacc[j][0], sacc[j][1], sacc[j][2], sacc[j][3],
                        qf[kc][0], qf[kc][1], qf[kc][2], qf[kc][3], b0, b1);
            }
        }

        // online softmax (rows g and g+8)
        float ml0 = -1e30f, ml1 = -1e30f;
        #pragma unroll
        for (int j = 0; j < 8; j++) {
            ml0 = fmaxf(ml0, fmaxf(sacc[j][0], sacc[j][1]));
            ml1 = fmaxf(ml1, fmaxf(sacc[j][2], sacc[j][3]));
        }
        ml0 = fmaxf(ml0, __shfl_xor_sync(0xffffffffu, ml0, 1));
        ml0 = fmaxf(ml0, __shfl_xor_sync(0xffffffffu, ml0, 2));
        ml1 = fmaxf(ml1, __shfl_xor_sync(0xffffffffu, ml1, 1));
        ml1 = fmaxf(ml1, __shfl_xor_sync(0xffffffffu, ml1, 2));

        float mn0 = fmaxf(m0, ml0), mn1 = fmaxf(m1, ml1);
        float f0 = exp2f((m0 - mn0) * C1), f1 = exp2f((m1 - mn1) * C1);
        m0 = mn0; m1 = mn1;
        const float mc0 = mn0 * C1, mc1 = mn1 * C1;

        uint32_t p01[8], p23[8];
        float ls0 = 0.f, ls1 = 0.f;
        #pragma unroll
        for (int j = 0; j < 8; j++) {
            __half2 e0 = __floats2half2_rn(fmaf(sacc[j][0], C1, -mc0),
                                           fmaf(sacc[j][1], C1, -mc0));
            __half2 e1 = __floats2half2_rn(fmaf(sacc[j][2], C1, -mc1),
                                           fmaf(sacc[j][3], C1, -mc1));
            uint32_t u0 = *(uint32_t*)&e0, u1 = *(uint32_t*)&e1;
            uint32_t r0, r1;
            asm("ex2.approx.f16x2 %0, %1;" : "=r"(r0) : "r"(u0));
            asm("ex2.approx.f16x2 %0, %1;" : "=r"(r1) : "r"(u1));
            p01[j] = r0; p23[j] = r1;
            float2 fA = __half22float2(*(__half2*)&r0);
            float2 fB = __half22float2(*(__half2*)&r1);
            ls0 += fA.x + fA.y;
            ls1 += fB.x + fB.y;
        }
        l0 = l0 * f0 + ls0;
        l1 = l1 * f1 + ls1;
        #pragma unroll
        for (int dn = 0; dn < 16; dn++) {
            oacc[dn][0] *= f0; oacc[dn][1] *= f0;
            oacc[dn][2] *= f1; oacc[dn][3] *= f1;
        }

        // O += P V  (16 d-tiles x 4 key-chunks)
        #pragma unroll
        for (int kk = 0; kk < 4; kk++) {
            uint32_t a0 = p01[2 * kk], a1 = p23[2 * kk];
            uint32_t a2 = p01[2 * kk + 1], a3 = p23[2 * kk + 1];
            #pragma unroll
            for (int dn = 0; dn < 16; dn++) {
                uint32_t addr = vbase + (uint32_t)(kk * 16 + (lane & 15)) * KVSTR + dn * 16;
                uint32_t b0, b1;
                asm volatile("ldmatrix.sync.aligned.m8n8.x2.trans.shared.b16 {%0,%1}, [%2];"
                             : "=r"(b0), "=r"(b1) : "r"(addr));
                mma_f16(oacc[dn][0], oacc[dn][1], oacc[dn][2], oacc[dn][3],
                        a0, a1, a2, a3, b0, b1);
            }
        }
        __syncthreads();
    }

    l0 += __shfl_xor_sync(0xffffffffu, l0, 1);
    l0 += __shfl_xor_sync(0xffffffffu, l0, 2);
    l1 += __shfl_xor_sync(0xffffffffu, l1, 1);
    l1 += __shfl_xor_sync(0xffffffffu, l1, 2);
    const float inv0 = 1.f / l0, inv1 = 1.f / l1;

    __half* c0row = ctx + (size_t)(qb + g) * H_DIM + h * HD;
    __half* c8row = c0row + (size_t)8 * H_DIM;
    #pragma unroll
    for (int dn = 0; dn < 16; dn++) {
        *(__half2*)(c0row + dn * 8 + 2 * c) =
            __floats2half2_rn(oacc[dn][0] * inv0, oacc[dn][1] * inv0);
        *(__half2*)(c8row + dn * 8 + 2 * c) =
            __floats2half2_rn(oacc[dn][2] * inv1, oacc[dn][3] * inv1);
    }
}

// ============== fp16 HMMA GEMM (R4-proven): C = A*B^T =======================
#define BK 32
#define AST 80
#define A_SBYTES (128 * AST)
#define B_SBYTES (256 * AST)
#define BUF_SBYTES (A_SBYTES + B_SBYTES)
#define NBUF 3
#define GEMM_SMEM_BYTES (NBUF * BUF_SBYTES)

template <int EPI, int OUTH>
__global__ void __launch_bounds__(256, 1)
gemm_h(const __half* __restrict__ A, const __half* __restrict__ B,
       const float* __restrict__ bias, const float* __restrict__ res,
       float alpha, void* __restrict__ Cv, int M, int N, int K) {
    extern __shared__ char smem[];

    const int tid  = threadIdx.x;
    const int lane = tid & 31;
    const int wid  = tid >> 5;
    const int wm   = wid & 1;
    const int wn   = wid >> 1;
    const int g    = lane >> 2;
    const int c    = lane & 3;

    const int m0 = blockIdx.x * 128;
    const int n0 = blockIdx.y * 256;

    const uint32_t sbase = (uint32_t)__cvta_generic_to_shared(smem);
    const int row4 = tid >> 2;
    const int kc   = tid & 3;

    float acc[4][8][4];
    #pragma unroll
    for (int i = 0; i < 4; i++)
        #pragma unroll
        for (int j = 0; j < 8; j++)
            #pragma unroll
            for (int q = 0; q < 4; q++) acc[i][j][q] = 0.f;

    const int nk = K >> 5;

    auto issue = [&](int kt, int b) {
        uint32_t ab = sbase + (uint32_t)b * BUF_SBYTES;
        uint32_t bb = ab + A_SBYTES;
        const __half* ag = A + (size_t)(m0 + row4) * K + kt * BK + kc * 8;
        const __half* bg = B + (size_t)(n0 + row4) * K + kt * BK + kc * 8;
        #pragma unroll
        for (int i = 0; i < 2; i++)
            cp_async16(ab + (uint32_t)(row4 + 64 * i) * AST + kc * 16,
                       ag + (size_t)(64 * i) * K);
        #pragma unroll
        for (int i = 0; i < 4; i++)
            cp_async16(bb + (uint32_t)(row4 + 64 * i) * AST + kc * 16,
                       bg + (size_t)(64 * i) * K);
        cp_commit();
    };

    issue(0, 0);
    issue(1, 1);

    for (int kt = 0; kt < nk; kt++) {
        const int b = kt % NBUF;
        if (kt + 2 < nk) { issue(kt + 2, (kt + 2) % NBUF); cp_wait<2>(); }
        else if (kt + 1 < nk) cp_wait<1>();
        else cp_wait<0>();
        __syncthreads();

        const char* As = smem + (size_t)b * BUF_SBYTES;
        const char* Bs = As + A_SBYTES;

        #pragma unroll
        for (int ks = 0; ks < 2; ks++) {
            const int kb = ks * 32;
            uint32_t af[4][4];
            uint32_t bf[8][2];
            #pragma unroll
            for (int mt = 0; mt < 4; mt++) {
                int r = wm * 64 + mt * 16 + g;
                af[mt][0] = *(const uint32_t*)(As + r * AST + kb + c * 4);
                af[mt][1] = *(const uint32_t*)(As + (r + 8) * AST + kb + c * 4);
                af[mt][2] = *(const uint32_t*)(As + r * AST + kb + 16 + c * 4);
                af[mt][3] = *(const uint32_t*)(As + (r + 8) * AST + kb + 16 + c * 4);
            }
            #pragma unroll
            for (int nt = 0; nt < 8; nt++) {
                int r = wn * 64 + nt * 8 + g;
                bf[nt][0] = *(const uint32_t*)(Bs + r * AST + kb + c * 4);
                bf[nt][1] = *(const uint32_t*)(Bs + r * AST + kb + 16 + c * 4);
            }
            #pragma unroll
            for (int mt = 0; mt < 4; mt++)
                #pragma unroll
                for (int nt = 0; nt < 8; nt++)
                    mma_f16(acc[mt][nt][0], acc[mt][nt][1],
                            acc[mt][nt][2], acc[mt][nt][3],
                            af[mt][0], af[mt][1], af[mt][2], af[mt][3],
                            bf[nt][0], bf[nt][1]);
        }
        __syncthreads();
    }

    #pragma unroll
    for (int mt = 0; mt < 4; mt++) {
        int r0 = m0 + wm * 64 + mt * 16 + g;
        int r1 = r0 + 8;
        #pragma unroll
        for (int nt = 0; nt < 8; nt++) {
            int col = n0 + wn * 64 + nt * 8 + 2 * c;
            float b0v = bias[col], b1v = bias[col + 1];

            float v0 = acc[mt][nt][0] + b0v;
            float v1 = acc[mt][nt][1] + b1v;
            float v2 = acc[mt][nt][2] + b0v;
            float v3 = acc[mt][nt][3] + b1v;
            if (EPI == 1) {
                v0 = gelu_tanh(v0); v1 = gelu_tanh(v1);
                v2 = gelu_tanh(v2); v3 = gelu_tanh(v3);
            }
            if (EPI == 2) {
                const float* rr0 = res + (size_t)r0 * N + col;
                const float* rr1 = res + (size_t)r1 * N + col;
                v0 += alpha * rr0[0]; v1 += alpha * rr0[1];
                v2 += alpha * rr1[0]; v3 += alpha * rr1[1];
            }
            if (OUTH) {
                __half* C = (__half*)Cv;
                *(__half2*)(C + (size_t)r0 * N + col) = __floats2half2_rn(v0, v1);
                *(__half2*)(C + (size_t)r1 * N + col) = __floats2half2_rn(v2, v3);
            } else {
                float* C = (float*)Cv;
                *(float2*)(C + (size_t)r0 * N + col) = make_float2(v0, v1);
                *(float2*)(C + (size_t)r1 * N + col) = make_float2(v2, v3);
            }
        }
    }
}

// ---------------- launch ----------------------------------------------------
extern "C" void kernel_launch(void* const* d_in, const int* in_sizes, int n_in,
                              void* d_out, int out_size) {
    const float* hidden  = (const float*)d_in[0];
    const float* cosc    = (const float*)d_in[4];
    const float* sinc    = (const float*)d_in[5];
    const float* ln1_w   = (const float*)d_in[6];
    const float* ln1_b   = (const float*)d_in[7];
    const float* qkv_w   = (const float*)d_in[8];
    const float* qkv_b   = (const float*)d_in[9];
    const float* dense_w = (const float*)d_in[10];
    const float* dense_b = (const float*)d_in[11];
    const float* ln2_w   = (const float*)d_in[12];
    const float* ln2_b   = (const float*)d_in[13];
    const float* mlp_w1  = (const float*)d_in[14];
    const float* mlp_b1  = (const float*)d_in[15];
    const float* mlp_w2  = (const float*)d_in[16];
    const float* mlp_b2  = (const float*)d_in[17];
    float* out = (float*)d_out;

    float *res1, *hid, *res2;
    __half *qkvh, *res1h, *res2h, *ctxh, *acth, *qkv_wh, *dense_wh, *w1h, *w2h;
    cudaGetSymbolAddress((void**)&res1,  g_res1);
    cudaGetSymbolAddress((void**)&hid,   g_hidden);
    cudaGetSymbolAddress((void**)&res2,  g_res2);
    cudaGetSymbolAddress((void**)&qkvh,  g_qkvh);
    cudaGetSymbolAddress((void**)&res1h, g_res1h);
    cudaGetSymbolAddress((void**)&res2h, g_res2h);
    cudaGetSymbolAddress((void**)&ctxh,  g_ctxh);
    cudaGetSymbolAddress((void**)&acth,  g_acth);
    cudaGetSymbolAddress((void**)&qkv_wh,   g_qkv_wh);
    cudaGetSymbolAddress((void**)&dense_wh, g_dense_wh);
    cudaGetSymbolAddress((void**)&w1h,      g_w1h);
    cudaGetSymbolAddress((void**)&w2h,      g_w2h);

    cudaFuncSetAttribute(gemm_h<0,1>, cudaFuncAttributeMaxDynamicSharedMemorySize, GEMM_SMEM_BYTES);
    cudaFuncSetAttribute(gemm_h<1,1>, cudaFuncAttributeMaxDynamicSharedMemorySize, GEMM_SMEM_BYTES);
    cudaFuncSetAttribute(gemm_h<2,0>, cudaFuncAttributeMaxDynamicSharedMemorySize, GEMM_SMEM_BYTES);
    cudaFuncSetAttribute(fattn_mma,   cudaFuncAttributeMaxDynamicSharedMemorySize, ATTN_SMEM);

    // 0. weight conversions fp32 -> fp16
    {
        int n;
        n = QKV3 * H_DIM;  f2h_kernel<<<n / 1024, 256>>>(qkv_w,   qkv_wh,   n);
        n = H_DIM * H_DIM; f2h_kernel<<<n / 1024, 256>>>(dense_w, dense_wh, n);
        n = INNER * H_DIM; f2h_kernel<<<n / 1024, 256>>>(mlp_w1,  w1h,      n);
        n = H_DIM * INNER; f2h_kernel<<<n / 1024, 256>>>(mlp_w2,  w2h,      n);
    }

    // 1. LN1
    ln_kernel<<<S_LEN, 256>>>(hidden, ln1_w, ln1_b, res1, res1h);

    // 2. QKV GEMM -> fp16 qkvh
    {
        dim3 grid(S_LEN / 128, QKV3 / 256);
        gemm_h<0,1><<<grid, 256, GEMM_SMEM_BYTES>>>(res1h, qkv_wh, qkv_b, res1, 0.f,
                                                    qkvh, S_LEN, QKV3, H_DIM);
    }

    // 3. RoPE (fp16 in-place)
    {
        dim3 grid(S_LEN, NH);
        rope_h_kernel<<<grid, 256>>>(qkvh, cosc, sinc);
    }

    // 4. HMMA flash attention (fp16 ctx out)
    {
        dim3 grid(S_LEN / 128, NH);
        fattn_mma<<<grid, 256, ATTN_SMEM>>>(qkvh, ctxh);
    }

    // 5. dense GEMM + alpha*residual
    {
        dim3 grid(S_LEN / 128, H_DIM / 256);
        gemm_h<2,0><<<grid, 256, GEMM_SMEM_BYTES>>>(ctxh, dense_wh, dense_b, res1, ALPHA,
                                                    hid, S_LEN, H_DIM, H_DIM);
    }

    // 6. LN2
    ln_kernel<<<S_LEN, 256>>>(hid, ln2_w, ln2_b, res2, res2h);

    // 7. MLP up + gelu (fp16 out)
    {
        dim3 grid(S_LEN / 128, INNER / 256);
        gemm_h<1,1><<<grid, 256, GEMM_SMEM_BYTES>>>(res2h, w1h, mlp_b1, res2, 0.f,
                                                    acth, S_LEN, INNER, H_DIM);
    }

    // 8. MLP down + alpha*residual -> output
    {
        dim3 grid(S_LEN / 128, H_DIM / 256);
        gemm_h<2,0><<<grid, 256, GEMM_SMEM_BYTES>>>(acth, w2h, mlp_b2, res2, ALPHA,
                                                    out, S_LEN, H_DIM, INNER);
    }
}

// round 14
// speedup vs baseline: 21.5687x; 1.0018x over previous
#include <cuda_runtime.h>
#include <cuda_fp16.h>
#include <math.h>
#include <stdint.h>

#define S_LEN 2048
#define H_DIM 4096
#define NH 32
#define HD 128
#define INNER 16384
#define QKV3 12288   // 3*H

static constexpr float ALPHA   = 7.4833147735478827f;  // sqrt(56)
static constexpr float SCALING = 1.0f;                 // layer_id+1 = 1
static constexpr float COEFF   = 11.313708498984761f;  // sqrt(128)*1
static constexpr float EPS     = 1e-5f;

// ---------------- scratch (device globals; no allocations allowed) ----------
__device__ __align__(1024) float  g_res1  [(size_t)S_LEN * H_DIM];
__device__ __align__(1024) float  g_hidden[(size_t)S_LEN * H_DIM];
__device__ __align__(1024) float  g_res2  [(size_t)S_LEN * H_DIM];

__device__ __align__(1024) __half g_qkvh  [(size_t)S_LEN * QKV3];
__device__ __align__(1024) __half g_res1h [(size_t)S_LEN * H_DIM];
__device__ __align__(1024) __half g_res2h [(size_t)S_LEN * H_DIM];
__device__ __align__(1024) __half g_ctxh  [(size_t)S_LEN * H_DIM];
__device__ __align__(1024) __half g_acth  [(size_t)S_LEN * INNER];

__device__ __align__(1024) __half g_qkv_wh  [(size_t)QKV3 * H_DIM];
__device__ __align__(1024) __half g_dense_wh[(size_t)H_DIM * H_DIM];
__device__ __align__(1024) __half g_w1h     [(size_t)INNER * H_DIM];
__device__ __align__(1024) __half g_w2h     [(size_t)H_DIM * INNER];

// ---------------- helpers ----------------
__device__ __forceinline__ float warpSum(float v) {
    #pragma unroll
    for (int o = 16; o > 0; o >>= 1) v += __shfl_xor_sync(0xffffffffu, v, o);
    return v;
}
__device__ __forceinline__ float gelu_tanh(float x) {
    float x3 = x * x * x;
    return 0.5f * x * (1.f + tanhf(0.7978845608028654f * (x + 0.044715f * x3)));
}

__device__ __forceinline__ void cp_async16(uint32_t sa, const void* g) {
    asm volatile("cp.async.cg.shared.global [%0], [%1], 16;\n" :: "r"(sa), "l"(g));
}
__device__ __forceinline__ void cp_commit() {
    asm volatile("cp.async.commit_group;\n");
}
template <int N>
__device__ __forceinline__ void cp_wait() {
    asm volatile("cp.async.wait_group %0;\n" :: "n"(N));
}

__device__ __forceinline__ void mma_f16(float& c0, float& c1, float& c2, float& c3,
                                        uint32_t a0, uint32_t a1, uint32_t a2, uint32_t a3,
                                        uint32_t b0, uint32_t b1) {
    asm volatile(
        "mma.sync.aligned.m16n8k16.row.col.f32.f16.f16.f32 "
        "{%0,%1,%2,%3}, {%4,%5,%6,%7}, {%8,%9}, {%0,%1,%2,%3};\n"
        : "+f"(c0), "+f"(c1), "+f"(c2), "+f"(c3)
        : "r"(a0), "r"(a1), "r"(a2), "r"(a3), "r"(b0), "r"(b1));
}

__device__ __forceinline__ void ldm_x4(uint32_t& r0, uint32_t& r1,
                                       uint32_t& r2, uint32_t& r3, uint32_t addr) {
    asm volatile("ldmatrix.sync.aligned.m8n8.x4.shared.b16 {%0,%1,%2,%3}, [%4];"
                 : "=r"(r0), "=r"(r1), "=r"(r2), "=r"(r3) : "r"(addr));
}
__device__ __forceinline__ void ldm_x4_trans(uint32_t& r0, uint32_t& r1,
                                             uint32_t& r2, uint32_t& r3, uint32_t addr) {
    asm volatile("ldmatrix.sync.aligned.m8n8.x4.trans.shared.b16 {%0,%1,%2,%3}, [%4];"
                 : "=r"(r0), "=r"(r1), "=r"(r2), "=r"(r3) : "r"(addr));
}

// ---------------- fp32 -> fp16 conversion ----------------
__global__ void f2h_kernel(const float* __restrict__ x, __half* __restrict__ y, int n) {
    int i = (blockIdx.x * blockDim.x + threadIdx.x) * 4;
    if (i < n) {
        float4 v = *(const float4*)(x + i);
        __half2* yo = (__half2*)(y + i);
        yo[0] = __floats2half2_rn(v.x, v.y);
        yo[1] = __floats2half2_rn(v.z, v.w);
    }
}

// ---------------- LayerNorm (fp32 out + fp16 out) ----------------
__global__ void ln_kernel(const float* __restrict__ x,
                          const float* __restrict__ w,
                          const float* __restrict__ b,
                          float* __restrict__ out,
                          __half* __restrict__ outh) {
    int row = blockIdx.x;
    int t = threadIdx.x;
    const float* xr = x + (size_t)row * H_DIM;
    float v[16];
    float s = 0.f;
    #pragma unroll
    for (int i = 0; i < 16; i++) { v[i] = xr[t + i * 256]; s += v[i]; }

    __shared__ float sh[8];
    __shared__ float s_mean, s_rstd;
    int lane = t & 31, wid = t >> 5;

    s = warpSum(s);
    if (lane == 0) sh[wid] = s;
    __syncthreads();
    if (t == 0) {
        float tot = 0.f;
        #pragma unroll
        for (int i = 0; i < 8; i++) tot += sh[i];
        s_mean = tot / (float)H_DIM;
    }
    __syncthreads();
    float m = s_mean;

    float vs = 0.f;
    #pragma unroll
    for (int i = 0; i < 16; i++) { float d = v[i] - m; vs += d * d; }
    vs = warpSum(vs);
    __syncthreads();
    if (lane == 0) sh[wid] = vs;
    __syncthreads();
    if (t == 0) {
        float tot = 0.f;
        #pragma unroll
        for (int i = 0; i < 8; i++) tot += sh[i];
        s_rstd = rsqrtf(tot / (float)H_DIM + EPS);
    }
    __syncthreads();
    float r = s_rstd;

    float* orow = out + (size_t)row * H_DIM;
    __half* hrow = outh + (size_t)row * H_DIM;
    #pragma unroll
    for (int i = 0; i < 16; i++) {
        int c = t + i * 256;
        float o = (v[i] - m) * r * w[c] + b[c];
        orow[c] = o;
        hrow[c] = __float2half_rn(o);
    }
}

// ---------------- RoPE (GLM dual rotary), fp16 in-place on qkvh -------------
__global__ void rope_h_kernel(__half* __restrict__ qkv,
                              const float* __restrict__ cosc,
                              const float* __restrict__ sinc) {
    int s = blockIdx.x, h = blockIdx.y;
    __half* base = qkv + (size_t)s * QKV3 + h * 384;
    __shared__ float buf[256];
    int t = threadIdx.x;
    buf[t] = __half2float(base[t]);
    __syncthreads();

    int isK  = (t >= 128) ? 128 : 0;
    int d    = t & 127;
    int half = d >> 6;
    int dd   = d & 63;

    int pos;
    if (half == 0) pos = (s < S_LEN - 1) ? s : (S_LEN - 2);
    else           pos = (s == S_LEN - 1) ? 1 : 0;

    float c  = cosc[pos * 64 + dd];
    float sn = sinc[pos * 64 + dd];

    int boff = isK + half * 64;
    float x   = buf[boff + dd];
    float rot = (dd < 32) ? -buf[boff + dd + 32] : buf[boff + dd - 32];
    base[t] = __float2half_rn(x * c + rot * sn);
}

// ============== HMMA flash attention: 128q CTA, 64-key tiles ================
// 8 warps, warp owns 16 q rows. K,V fp16 row-major in smem (272B stride ->
// conflict-free ldmatrix: 8 rows x 68 words hit all 32 banks once).
// QK b-frags + PV b-frags via ldmatrix.x4 (trans for PV).

#define KVSTR 272
#define TILE_B (64 * KVSTR)          // 17408
#define ATTN_SMEM (2 * 2 * TILE_B)   // 69632

__global__ void __launch_bounds__(256, 1)
fattn_mma(const __half* __restrict__ qkv, __half* __restrict__ ctx) {
    extern __shared__ char smem[];
    const uint32_t sbase = (uint32_t)__cvta_generic_to_shared(smem);
    const int tid  = threadIdx.x;
    const int lane = tid & 31;
    const int wid  = tid >> 5;
    const int g    = lane >> 2;
    const int c    = lane & 3;
    const int qb   = blockIdx.x * 128 + wid * 16;
    const int h    = blockIdx.y;

    // Q fragments (held in registers for all K tiles)
    uint32_t qf[8][4];
    {
        const __half* q0 = qkv + (size_t)(qb + g) * QKV3 + h * 384;
        const __half* q8 = q0 + (size_t)8 * QKV3;
        #pragma unroll
        for (int kc = 0; kc < 8; kc++) {
            qf[kc][0] = *(const uint32_t*)(q0 + kc * 16 + 2 * c);
            qf[kc][1] = *(const uint32_t*)(q8 + kc * 16 + 2 * c);
            qf[kc][2] = *(const uint32_t*)(q0 + kc * 16 + 2 * c + 8);
            qf[kc][3] = *(const uint32_t*)(q8 + kc * 16 + 2 * c + 8);
        }
    }

    float oacc[16][4];
    #pragma unroll
    for (int dn = 0; dn < 16; dn++)
        #pragma unroll
        for (int q = 0; q < 4; q++) oacc[dn][q] = 0.f;
    float m0 = -1e30f, m1 = -1e30f, l0 = 0.f, l1 = 0.f;

    auto load_tile = [&](int kt, int b) {
        uint32_t kb = sbase + (uint32_t)b * (2 * TILE_B);
        uint32_t vb = kb + TILE_B;
        const int kbase = kt * 64;
        #pragma unroll
        for (int i = 0; i < 4; i++) {
            int id = tid + 256 * i;
            int row = id >> 4, ch = id & 15;
            const __half* src = qkv + (size_t)(kbase + row) * QKV3 + h * 384 + 128 + ch * 8;
            cp_async16(kb + (uint32_t)row * KVSTR + ch * 16, src);
            cp_async16(vb + (uint32_t)row * KVSTR + ch * 16, src + 128);
        }
        cp_commit();
    };

    load_tile(0, 0);
    const float C1 = 0.12752697f;   // log2(e) * SCALING / COEFF

    for (int kt = 0; kt < S_LEN / 64; kt++) {
        const int b = kt & 1;
        if (kt + 1 < S_LEN / 64) { load_tile(kt + 1, b ^ 1); cp_wait<1>(); }
        else                     cp_wait<0>();
        __syncthreads();

        const uint32_t kbb = sbase + (uint32_t)b * (2 * TILE_B);
        const uint32_t vbase = kbb + TILE_B;

        // S = Q K^T  (8 n-tiles of 8 keys); b-frags via ldmatrix.x4
        float sacc[8][4];
        #pragma unroll
        for (int j = 0; j < 8; j++) {
            sacc[j][0] = sacc[j][1] = sacc[j][2] = sacc[j][3] = 0.f;
            #pragma unroll
            for (int kc = 0; kc < 8; kc += 2) {
                uint32_t addr = kbb + (uint32_t)(j * 8 + (lane & 7)) * KVSTR
                              + kc * 32 + (lane >> 3) * 16;
                uint32_t b0, b1, b2, b3;
                ldm_x4(b0, b1, b2, b3, addr);
                mma_f16(sacc[j][0], sacc[j][1], sacc[j][2], sacc[j][3],
                        qf[kc][0], qf[kc][1], qf[kc][2], qf[kc][3], b0, b1);
                mma_f16(sacc[j][0], sacc[j][1], sacc[j][2], sacc[j][3],
                        qf[kc + 1][0], qf[kc + 1][1], qf[kc + 1][2], qf[kc + 1][3], b2, b3);
            }
        }

        // online softmax (rows g and g+8)
        float ml0 = -1e30f, ml1 = -1e30f;
        #pragma unroll
        for (int j = 0; j < 8; j++) {
            ml0 = fmaxf(ml0, fmaxf(sacc[j][0], sacc[j][1]));
            ml1 = fmaxf(ml1, fmaxf(sacc[j][2], sacc[j][3]));
        }
        ml0 = fmaxf(ml0, __shfl_xor_sync(0xffffffffu, ml0, 1));
        ml0 = fmaxf(ml0, __shfl_xor_sync(0xffffffffu, ml0, 2));
        ml1 = fmaxf(ml1, __shfl_xor_sync(0xffffffffu, ml1, 1));
        ml1 = fmaxf(ml1, __shfl_xor_sync(0xffffffffu, ml1, 2));

        float mn0 = fmaxf(m0, ml0), mn1 = fmaxf(m1, ml1);
        float f0 = exp2f((m0 - mn0) * C1), f1 = exp2f((m1 - mn1) * C1);
        m0 = mn0; m1 = mn1;
        const float mc0 = mn0 * C1, mc1 = mn1 * C1;

        uint32_t p01[8], p23[8];
        float ls0 = 0.f, ls1 = 0.f;
        #pragma unroll
        for (int j = 0; j < 8; j++) {
            __half2 e0 = __floats2half2_rn(fmaf(sacc[j][0], C1, -mc0),
                                           fmaf(sacc[j][1], C1, -mc0));
            __half2 e1 = __floats2half2_rn(fmaf(sacc[j][2], C1, -mc1),
                                           fmaf(sacc[j][3], C1, -mc1));
            uint32_t u0 = *(uint32_t*)&e0, u1 = *(uint32_t*)&e1;
            uint32_t r0, r1;
            asm("ex2.approx.f16x2 %0, %1;" : "=r"(r0) : "r"(u0));
            asm("ex2.approx.f16x2 %0, %1;" : "=r"(r1) : "r"(u1));
            p01[j] = r0; p23[j] = r1;
            float2 fA = __half22float2(*(__half2*)&r0);
            float2 fB = __half22float2(*(__half2*)&r1);
            ls0 += fA.x + fA.y;
            ls1 += fB.x + fB.y;
        }
        l0 = l0 * f0 + ls0;
        l1 = l1 * f1 + ls1;
        #pragma unroll
        for (int dn = 0; dn < 16; dn++) {
            oacc[dn][0] *= f0; oacc[dn][1] *= f0;
            oacc[dn][2] *= f1; oacc[dn][3] *= f1;
        }

        // O += P V : b-frags via ldmatrix.x4.trans (covers dn, dn+1)
        #pragma unroll
        for (int kk = 0; kk < 4; kk++) {
            uint32_t a0 = p01[2 * kk], a1 = p23[2 * kk];
            uint32_t a2 = p01[2 * kk + 1], a3 = p23[2 * kk + 1];
            #pragma unroll
            for (int dn = 0; dn < 16; dn += 2) {
                uint32_t addr = vbase + (uint32_t)(kk * 16 + (lane & 15)) * KVSTR
                              + (dn + (lane >> 4)) * 16;
                uint32_t b0, b1, b2, b3;
                ldm_x4_trans(b0, b1, b2, b3, addr);
                mma_f16(oacc[dn][0], oacc[dn][1], oacc[dn][2], oacc[dn][3],
                        a0, a1, a2, a3, b0, b1);
                mma_f16(oacc[dn + 1][0], oacc[dn + 1][1], oacc[dn + 1][2], oacc[dn + 1][3],
                        a0, a1, a2, a3, b2, b3);
            }
        }
        __syncthreads();
    }

    l0 += __shfl_xor_sync(0xffffffffu, l0, 1);
    l0 += __shfl_xor_sync(0xffffffffu, l0, 2);
    l1 += __shfl_xor_sync(0xffffffffu, l1, 1);
    l1 += __shfl_xor_sync(0xffffffffu, l1, 2);
    const float inv0 = 1.f / l0, inv1 = 1.f / l1;

    __half* c0row = ctx + (size_t)(qb + g) * H_DIM + h * HD;
    __half* c8row = c0row + (size_t)8 * H_DIM;
    #pragma unroll
    for (int dn = 0; dn < 16; dn++) {
        *(__half2*)(c0row + dn * 8 + 2 * c) =
            __floats2half2_rn(oacc[dn][0] * inv0, oacc[dn][1] * inv0);
        *(__half2*)(c8row + dn * 8 + 2 * c) =
            __floats2half2_rn(oacc[dn][2] * inv1, oacc[dn][3] * inv1);
    }
}

// ============== fp16 HMMA GEMM with ldmatrix fragments: C = A*B^T ===========
#define BK 32
#define AST 80
#define A_SBYTES (128 * AST)
#define B_SBYTES (256 * AST)
#define BUF_SBYTES (A_SBYTES + B_SBYTES)
#define NBUF 3
#define GEMM_SMEM_BYTES (NBUF * BUF_SBYTES)

template <int EPI, int OUTH>
__global__ void __launch_bounds__(256, 1)
gemm_h(const __half* __restrict__ A, const __half* __restrict__ B,
       const float* __restrict__ bias, const float* __restrict__ res,
       float alpha, void* __restrict__ Cv, int M, int N, int K) {
    extern __shared__ char smem[];

    const int tid  = threadIdx.x;
    const int lane = tid & 31;
    const int wid  = tid >> 5;
    const int wm   = wid & 1;
    const int wn   = wid >> 1;
    const int g    = lane >> 2;
    const int c    = lane & 3;

    const int m0 = blockIdx.x * 128;
    const int n0 = blockIdx.y * 256;

    const uint32_t sbase = (uint32_t)__cvta_generic_to_shared(smem);
    const int row4 = tid >> 2;
    const int kc   = tid & 3;

    float acc[4][8][4];
    #pragma unroll
    for (int i = 0; i < 4; i++)
        #pragma unroll
        for (int j = 0; j < 8; j++)
            #pragma unroll
            for (int q = 0; q < 4; q++) acc[i][j][q] = 0.f;

    const int nk = K >> 5;

    auto issue = [&](int kt, int b) {
        uint32_t ab = sbase + (uint32_t)b * BUF_SBYTES;
        uint32_t bb = ab + A_SBYTES;
        const __half* ag = A + (size_t)(m0 + row4) * K + kt * BK + kc * 8;
        const __half* bg = B + (size_t)(n0 + row4) * K + kt * BK + kc * 8;
        #pragma unroll
        for (int i = 0; i < 2; i++)
            cp_async16(ab + (uint32_t)(row4 + 64 * i) * AST + kc * 16,
                       ag + (size_t)(64 * i) * K);
        #pragma unroll
        for (int i = 0; i < 4; i++)
            cp_async16(bb + (uint32_t)(row4 + 64 * i) * AST + kc * 16,
                       bg + (size_t)(64 * i) * K);
        cp_commit();
    };

    issue(0, 0);
    issue(1, 1);

    // ldmatrix address components (constant per thread)
    const int a_row = wm * 64 + (lane & 15);      // + mt*16
    const int a_cb  = (lane & 16);                // 0 | 16 bytes
    const int b_row = wn * 64 + (lane & 7) + ((lane >> 4) << 3);  // + nt*8 (pairs)
    const int b_cb  = ((lane >> 3) & 1) * 16;     // 0 | 16 bytes

    for (int kt = 0; kt < nk; kt++) {
        const int b = kt % NBUF;
        if (kt + 2 < nk) { issue(kt + 2, (kt + 2) % NBUF); cp_wait<2>(); }
        else if (kt + 1 < nk) cp_wait<1>();
        else cp_wait<0>();
        __syncthreads();

        const uint32_t As = sbase + (uint32_t)b * BUF_SBYTES;
        const uint32_t Bs = As + A_SBYTES;

        #pragma unroll
        for (int ks = 0; ks < 2; ks++) {
            const int kb = ks * 32;
            uint32_t af[4][4];
            uint32_t bf[8][2];
            #pragma unroll
            for (int mt = 0; mt < 4; mt++)
                ldm_x4(af[mt][0], af[mt][1], af[mt][2], af[mt][3],
                       As + (uint32_t)(a_row + mt * 16) * AST + kb + a_cb);
            #pragma unroll
            for (int nt = 0; nt < 8; nt += 2)
                ldm_x4(bf[nt][0], bf[nt][1], bf[nt + 1][0], bf[nt + 1][1],
                       Bs + (uint32_t)(b_row + nt * 8) * AST + kb + b_cb);
            #pragma unroll
            for (int mt = 0; mt < 4; mt++)
                #pragma unroll
                for (int nt = 0; nt < 8; nt++)
                    mma_f16(acc[mt][nt][0], acc[mt][nt][1],
                            acc[mt][nt][2], acc[mt][nt][3],
                            af[mt][0], af[mt][1], af[mt][2], af[mt][3],
                            bf[nt][0], bf[nt][1]);
        }
        __syncthreads();
    }

    #pragma unroll
    for (int mt = 0; mt < 4; mt++) {
        int r0 = m0 + wm * 64 + mt * 16 + g;
        int r1 = r0 + 8;
        #pragma unroll
        for (int nt = 0; nt < 8; nt++) {
            int col = n0 + wn * 64 + nt * 8 + 2 * c;
            float b0v = bias[col], b1v = bias[col + 1];

            float v0 = acc[mt][nt][0] + b0v;
            float v1 = acc[mt][nt][1] + b1v;
            float v2 = acc[mt][nt][2] + b0v;
            float v3 = acc[mt][nt][3] + b1v;
            if (EPI == 1) {
                v0 = gelu_tanh(v0); v1 = gelu_tanh(v1);
                v2 = gelu_tanh(v2); v3 = gelu_tanh(v3);
            }
            if (EPI == 2) {
                const float* rr0 = res + (size_t)r0 * N + col;
                const float* rr1 = res + (size_t)r1 * N + col;
                v0 += alpha * rr0[0]; v1 += alpha * rr0[1];
                v2 += alpha * rr1[0]; v3 += alpha * rr1[1];
            }
            if (OUTH) {
                __half* C = (__half*)Cv;
                *(__half2*)(C + (size_t)r0 * N + col) = __floats2half2_rn(v0, v1);
                *(__half2*)(C + (size_t)r1 * N + col) = __floats2half2_rn(v2, v3);
            } else {
                float* C = (float*)Cv;
                *(float2*)(C + (size_t)r0 * N + col) = make_float2(v0, v1);
                *(float2*)(C + (size_t)r1 * N + col) = make_float2(v2, v3);
            }
        }
    }
}

// ---------------- launch ----------------------------------------------------
extern "C" void kernel_launch(void* const* d_in, const int* in_sizes, int n_in,
                              void* d_out, int out_size) {
    const float* hidden  = (const float*)d_in[0];
    const float* cosc    = (const float*)d_in[4];
    const float* sinc    = (const float*)d_in[5];
    const float* ln1_w   = (const float*)d_in[6];
    const float* ln1_b   = (const float*)d_in[7];
    const float* qkv_w   = (const float*)d_in[8];
    const float* qkv_b   = (const float*)d_in[9];
    const float* dense_w = (const float*)d_in[10];
    const float* dense_b = (const float*)d_in[11];
    const float* ln2_w   = (const float*)d_in[12];
    const float* ln2_b   = (const float*)d_in[13];
    const float* mlp_w1  = (const float*)d_in[14];
    const float* mlp_b1  = (const float*)d_in[15];
    const float* mlp_w2  = (const float*)d_in[16];
    const float* mlp_b2  = (const float*)d_in[17];
    float* out = (float*)d_out;

    float *res1, *hid, *res2;
    __half *qkvh, *res1h, *res2h, *ctxh, *acth, *qkv_wh, *dense_wh, *w1h, *w2h;
    cudaGetSymbolAddress((void**)&res1,  g_res1);
    cudaGetSymbolAddress((void**)&hid,   g_hidden);
    cudaGetSymbolAddress((void**)&res2,  g_res2);
    cudaGetSymbolAddress((void**)&qkvh,  g_qkvh);
    cudaGetSymbolAddress((void**)&res1h, g_res1h);
    cudaGetSymbolAddress((void**)&res2h, g_res2h);
    cudaGetSymbolAddress((void**)&ctxh,  g_ctxh);
    cudaGetSymbolAddress((void**)&acth,  g_acth);
    cudaGetSymbolAddress((void**)&qkv_wh,   g_qkv_wh);
    cudaGetSymbolAddress((void**)&dense_wh, g_dense_wh);
    cudaGetSymbolAddress((void**)&w1h,      g_w1h);
    cudaGetSymbolAddress((void**)&w2h,      g_w2h);

    cudaFuncSetAttribute(gemm_h<0,1>, cudaFuncAttributeMaxDynamicSharedMemorySize, GEMM_SMEM_BYTES);
    cudaFuncSetAttribute(gemm_h<1,1>, cudaFuncAttributeMaxDynamicSharedMemorySize, GEMM_SMEM_BYTES);
    cudaFuncSetAttribute(gemm_h<2,0>, cudaFuncAttributeMaxDynamicSharedMemorySize, GEMM_SMEM_BYTES);
    cudaFuncSetAttribute(fattn_mma,   cudaFuncAttributeMaxDynamicSharedMemorySize, ATTN_SMEM);

    // 0. weight conversions fp32 -> fp16
    {
        int n;
        n = QKV3 * H_DIM;  f2h_kernel<<<n / 1024, 256>>>(qkv_w,   qkv_wh,   n);
        n = H_DIM * H_DIM; f2h_kernel<<<n / 1024, 256>>>(dense_w, dense_wh, n);
        n = INNER * H_DIM; f2h_kernel<<<n / 1024, 256>>>(mlp_w1,  w1h,      n);
        n = H_DIM * INNER; f2h_kernel<<<n / 1024, 256>>>(mlp_w2,  w2h,      n);
    }

    // 1. LN1
    ln_kernel<<<S_LEN, 256>>>(hidden, ln1_w, ln1_b, res1, res1h);

    // 2. QKV GEMM -> fp16 qkvh
    {
        dim3 grid(S_LEN / 128, QKV3 / 256);
        gemm_h<0,1><<<grid, 256, GEMM_SMEM_BYTES>>>(res1h, qkv_wh, qkv_b, res1, 0.f,
                                                    qkvh, S_LEN, QKV3, H_DIM);
    }

    // 3. RoPE (fp16 in-place)
    {
        dim3 grid(S_LEN, NH);
        rope_h_kernel<<<grid, 256>>>(qkvh, cosc, sinc);
    }

    // 4. HMMA flash attention (fp16 ctx out)
    {
        dim3 grid(S_LEN / 128, NH);
        fattn_mma<<<grid, 256, ATTN_SMEM>>>(qkvh, ctxh);
    }

    // 5. dense GEMM + alpha*residual
    {
        dim3 grid(S_LEN / 128, H_DIM / 256);
        gemm_h<2,0><<<grid, 256, GEMM_SMEM_BYTES>>>(ctxh, dense_wh, dense_b, res1, ALPHA,
                                                    hid, S_LEN, H_DIM, H_DIM);
    }

    // 6. LN2
    ln_kernel<<<S_LEN, 256>>>(hid, ln2_w, ln2_b, res2, res2h);

    // 7. MLP up + gelu (fp16 out)
    {
        dim3 grid(S_LEN / 128, INNER / 256);
        gemm_h<1,1><<<grid, 256, GEMM_SMEM_BYTES>>>(res2h, w1h, mlp_b1, res2, 0.f,
                                                    acth, S_LEN, INNER, H_DIM);
    }

    // 8. MLP down + alpha*residual -> output
    {
        dim3 grid(S_LEN / 128, H_DIM / 256);
        gemm_h<2,0><<<grid, 256, GEMM_SMEM_BYTES>>>(acth, w2h, mlp_b2, res2, ALPHA,
                                                    out, S_LEN, H_DIM, INNER);
    }
}

// round 15
// speedup vs baseline: 21.5784x; 1.0004x over previous
#include <cuda_runtime.h>
#include <cuda_fp16.h>
#include <math.h>
#include <stdint.h>

#define S_LEN 2048
#define H_DIM 4096
#define NH 32
#define HD 128
#define INNER 16384
#define QKV3 12288   // 3*H

static constexpr float ALPHA   = 7.4833147735478827f;  // sqrt(56)
static constexpr float SCALING = 1.0f;                 // layer_id+1 = 1
static constexpr float COEFF   = 11.313708498984761f;  // sqrt(128)*1
static constexpr float EPS     = 1e-5f;

// ---------------- scratch (device globals; no allocations allowed) ----------
__device__ __align__(1024) float  g_res1  [(size_t)S_LEN * H_DIM];
__device__ __align__(1024) float  g_hidden[(size_t)S_LEN * H_DIM];
__device__ __align__(1024) float  g_res2  [(size_t)S_LEN * H_DIM];

__device__ __align__(1024) __half g_qkvh  [(size_t)S_LEN * QKV3];
__device__ __align__(1024) __half g_res1h [(size_t)S_LEN * H_DIM];
__device__ __align__(1024) __half g_res2h [(size_t)S_LEN * H_DIM];
__device__ __align__(1024) __half g_ctxh  [(size_t)S_LEN * H_DIM];
__device__ __align__(1024) __half g_acth  [(size_t)S_LEN * INNER];

__device__ __align__(1024) __half g_qkv_wh  [(size_t)QKV3 * H_DIM];
__device__ __align__(1024) __half g_dense_wh[(size_t)H_DIM * H_DIM];
__device__ __align__(1024) __half g_w1h     [(size_t)INNER * H_DIM];
__device__ __align__(1024) __half g_w2h     [(size_t)H_DIM * INNER];

// ---------------- helpers ----------------
__device__ __forceinline__ float warpSum(float v) {
    #pragma unroll
    for (int o = 16; o > 0; o >>= 1) v += __shfl_xor_sync(0xffffffffu, v, o);
    return v;
}
__device__ __forceinline__ float gelu_tanh(float x) {
    float x3 = x * x * x;
    return 0.5f * x * (1.f + tanhf(0.7978845608028654f * (x + 0.044715f * x3)));
}

__device__ __forceinline__ void cp_async16(uint32_t sa, const void* g) {
    asm volatile("cp.async.cg.shared.global [%0], [%1], 16;\n" :: "r"(sa), "l"(g));
}
__device__ __forceinline__ void cp_commit() {
    asm volatile("cp.async.commit_group;\n");
}
template <int N>
__device__ __forceinline__ void cp_wait() {
    asm volatile("cp.async.wait_group %0;\n" :: "n"(N));
}

__device__ __forceinline__ void mma_f16(float& c0, float& c1, float& c2, float& c3,
                                        uint32_t a0, uint32_t a1, uint32_t a2, uint32_t a3,
                                        uint32_t b0, uint32_t b1) {
    asm volatile(
        "mma.sync.aligned.m16n8k16.row.col.f32.f16.f16.f32 "
        "{%0,%1,%2,%3}, {%4,%5,%6,%7}, {%8,%9}, {%0,%1,%2,%3};\n"
        : "+f"(c0), "+f"(c1), "+f"(c2), "+f"(c3)
        : "r"(a0), "r"(a1), "r"(a2), "r"(a3), "r"(b0), "r"(b1));
}

__device__ __forceinline__ void ldm_x4(uint32_t& r0, uint32_t& r1,
                                       uint32_t& r2, uint32_t& r3, uint32_t addr) {
    asm volatile("ldmatrix.sync.aligned.m8n8.x4.shared.b16 {%0,%1,%2,%3}, [%4];"
                 : "=r"(r0), "=r"(r1), "=r"(r2), "=r"(r3) : "r"(addr));
}
__device__ __forceinline__ void ldm_x4_trans(uint32_t& r0, uint32_t& r1,
                                             uint32_t& r2, uint32_t& r3, uint32_t addr) {
    asm volatile("ldmatrix.sync.aligned.m8n8.x4.trans.shared.b16 {%0,%1,%2,%3}, [%4];"
                 : "=r"(r0), "=r"(r1), "=r"(r2), "=r"(r3) : "r"(addr));
}

// ---------------- fp32 -> fp16 conversion ----------------
__global__ void f2h_kernel(const float* __restrict__ x, __half* __restrict__ y, int n) {
    int i = (blockIdx.x * blockDim.x + threadIdx.x) * 4;
    if (i < n) {
        float4 v = *(const float4*)(x + i);
        __half2* yo = (__half2*)(y + i);
        yo[0] = __floats2half2_rn(v.x, v.y);
        yo[1] = __floats2half2_rn(v.z, v.w);
    }
}

// ---------------- LayerNorm (fp32 out + fp16 out) ----------------
__global__ void ln_kernel(const float* __restrict__ x,
                          const float* __restrict__ w,
                          const float* __restrict__ b,
                          float* __restrict__ out,
                          __half* __restrict__ outh) {
    int row = blockIdx.x;
    int t = threadIdx.x;
    const float* xr = x + (size_t)row * H_DIM;
    float v[16];
    float s = 0.f;
    #pragma unroll
    for (int i = 0; i < 16; i++) { v[i] = xr[t + i * 256]; s += v[i]; }

    __shared__ float sh[8];
    __shared__ float s_mean, s_rstd;
    int lane = t & 31, wid = t >> 5;

    s = warpSum(s);
    if (lane == 0) sh[wid] = s;
    __syncthreads();
    if (t == 0) {
        float tot = 0.f;
        #pragma unroll
        for (int i = 0; i < 8; i++) tot += sh[i];
        s_mean = tot / (float)H_DIM;
    }
    __syncthreads();
    float m = s_mean;

    float vs = 0.f;
    #pragma unroll
    for (int i = 0; i < 16; i++) { float d = v[i] - m; vs += d * d; }
    vs = warpSum(vs);
    __syncthreads();
    if (lane == 0) sh[wid] = vs;
    __syncthreads();
    if (t == 0) {
        float tot = 0.f;
        #pragma unroll
        for (int i = 0; i < 8; i++) tot += sh[i];
        s_rstd = rsqrtf(tot / (float)H_DIM + EPS);
    }
    __syncthreads();
    float r = s_rstd;

    float* orow = out + (size_t)row * H_DIM;
    __half* hrow = outh + (size_t)row * H_DIM;
    #pragma unroll
    for (int i = 0; i < 16; i++) {
        int c = t + i * 256;
        float o = (v[i] - m) * r * w[c] + b[c];
        orow[c] = o;
        hrow[c] = __float2half_rn(o);
    }
}

// ---------------- RoPE (GLM dual rotary), fp16 in-place on qkvh -------------
__global__ void rope_h_kernel(__half* __restrict__ qkv,
                              const float* __restrict__ cosc,
                              const float* __restrict__ sinc) {
    int s = blockIdx.x, h = blockIdx.y;
    __half* base = qkv + (size_t)s * QKV3 + h * 384;
    __shared__ float buf[256];
    int t = threadIdx.x;
    buf[t] = __half2float(base[t]);
    __syncthreads();

    int isK  = (t >= 128) ? 128 : 0;
    int d    = t & 127;
    int half = d >> 6;
    int dd   = d & 63;

    int pos;
    if (half == 0) pos = (s < S_LEN - 1) ? s : (S_LEN - 2);
    else           pos = (s == S_LEN - 1) ? 1 : 0;

    float c  = cosc[pos * 64 + dd];
    float sn = sinc[pos * 64 + dd];

    int boff = isK + half * 64;
    float x   = buf[boff + dd];
    float rot = (dd < 32) ? -buf[boff + dd + 32] : buf[boff + dd - 32];
    base[t] = __float2half_rn(x * c + rot * sn);
}

// ============== HMMA flash attention: 128q CTA, 64-key tiles ================
#define KVSTR 272
#define TILE_B (64 * KVSTR)          // 17408
#define ATTN_SMEM (2 * 2 * TILE_B)   // 69632

__global__ void __launch_bounds__(256, 1)
fattn_mma(const __half* __restrict__ qkv, __half* __restrict__ ctx) {
    extern __shared__ char smem[];
    const uint32_t sbase = (uint32_t)__cvta_generic_to_shared(smem);
    const int tid  = threadIdx.x;
    const int lane = tid & 31;
    const int wid  = tid >> 5;
    const int g    = lane >> 2;
    const int c    = lane & 3;
    const int qb   = blockIdx.x * 128 + wid * 16;
    const int h    = blockIdx.y;

    // Q fragments (held in registers for all K tiles)
    uint32_t qf[8][4];
    {
        const __half* q0 = qkv + (size_t)(qb + g) * QKV3 + h * 384;
        const __half* q8 = q0 + (size_t)8 * QKV3;
        #pragma unroll
        for (int kc = 0; kc < 8; kc++) {
            qf[kc][0] = *(const uint32_t*)(q0 + kc * 16 + 2 * c);
            qf[kc][1] = *(const uint32_t*)(q8 + kc * 16 + 2 * c);
            qf[kc][2] = *(const uint32_t*)(q0 + kc * 16 + 2 * c + 8);
            qf[kc][3] = *(const uint32_t*)(q8 + kc * 16 + 2 * c + 8);
        }
    }

    float oacc[16][4];
    #pragma unroll
    for (int dn = 0; dn < 16; dn++)
        #pragma unroll
        for (int q = 0; q < 4; q++) oacc[dn][q] = 0.f;
    float m0 = -1e30f, m1 = -1e30f, l0 = 0.f, l1 = 0.f;

    auto load_tile = [&](int kt, int b) {
        uint32_t kb = sbase + (uint32_t)b * (2 * TILE_B);
        uint32_t vb = kb + TILE_B;
        const int kbase = kt * 64;
        #pragma unroll
        for (int i = 0; i < 4; i++) {
            int id = tid + 256 * i;
            int row = id >> 4, ch = id & 15;
            const __half* src = qkv + (size_t)(kbase + row) * QKV3 + h * 384 + 128 + ch * 8;
            cp_async16(kb + (uint32_t)row * KVSTR + ch * 16, src);
            cp_async16(vb + (uint32_t)row * KVSTR + ch * 16, src + 128);
        }
        cp_commit();
    };

    load_tile(0, 0);
    const float C1 = 0.12752697f;   // log2(e) * SCALING / COEFF

    for (int kt = 0; kt < S_LEN / 64; kt++) {
        const int b = kt & 1;
        if (kt + 1 < S_LEN / 64) { load_tile(kt + 1, b ^ 1); cp_wait<1>(); }
        else                     cp_wait<0>();
        __syncthreads();

        const uint32_t kbb = sbase + (uint32_t)b * (2 * TILE_B);
        const uint32_t vbase = kbb + TILE_B;

        // S = Q K^T  (8 n-tiles of 8 keys); b-frags via ldmatrix.x4
        float sacc[8][4];
        #pragma unroll
        for (int j = 0; j < 8; j++) {
            sacc[j][0] = sacc[j][1] = sacc[j][2] = sacc[j][3] = 0.f;
            #pragma unroll
            for (int kc = 0; kc < 8; kc += 2) {
                uint32_t addr = kbb + (uint32_t)(j * 8 + (lane & 7)) * KVSTR
                              + kc * 32 + (lane >> 3) * 16;
                uint32_t b0, b1, b2, b3;
                ldm_x4(b0, b1, b2, b3, addr);
                mma_f16(sacc[j][0], sacc[j][1], sacc[j][2], sacc[j][3],
                        qf[kc][0], qf[kc][1], qf[kc][2], qf[kc][3], b0, b1);
                mma_f16(sacc[j][0], sacc[j][1], sacc[j][2], sacc[j][3],
                        qf[kc + 1][0], qf[kc + 1][1], qf[kc + 1][2], qf[kc + 1][3], b2, b3);
            }
        }

        // online softmax (rows g and g+8)
        float ml0 = -1e30f, ml1 = -1e30f;
        #pragma unroll
        for (int j = 0; j < 8; j++) {
            ml0 = fmaxf(ml0, fmaxf(sacc[j][0], sacc[j][1]));
            ml1 = fmaxf(ml1, fmaxf(sacc[j][2], sacc[j][3]));
        }
        ml0 = fmaxf(ml0, __shfl_xor_sync(0xffffffffu, ml0, 1));
        ml0 = fmaxf(ml0, __shfl_xor_sync(0xffffffffu, ml0, 2));
        ml1 = fmaxf(ml1, __shfl_xor_sync(0xffffffffu, ml1, 1));
        ml1 = fmaxf(ml1, __shfl_xor_sync(0xffffffffu, ml1, 2));

        float mn0 = fmaxf(m0, ml0), mn1 = fmaxf(m1, ml1);
        float f0 = exp2f((m0 - mn0) * C1), f1 = exp2f((m1 - mn1) * C1);
        m0 = mn0; m1 = mn1;
        const float mc0 = mn0 * C1, mc1 = mn1 * C1;

        uint32_t p01[8], p23[8];
        float ls0 = 0.f, ls1 = 0.f;
        #pragma unroll
        for (int j = 0; j < 8; j++) {
            __half2 e0 = __floats2half2_rn(fmaf(sacc[j][0], C1, -mc0),
                                           fmaf(sacc[j][1], C1, -mc0));
            __half2 e1 = __floats2half2_rn(fmaf(sacc[j][2], C1, -mc1),
                                           fmaf(sacc[j][3], C1, -mc1));
            uint32_t u0 = *(uint32_t*)&e0, u1 = *(uint32_t*)&e1;
            uint32_t r0, r1;
            asm("ex2.approx.f16x2 %0, %1;" : "=r"(r0) : "r"(u0));
            asm("ex2.approx.f16x2 %0, %1;" : "=r"(r1) : "r"(u1));
            p01[j] = r0; p23[j] = r1;
            float2 fA = __half22float2(*(__half2*)&r0);
            float2 fB = __half22float2(*(__half2*)&r1);
            ls0 += fA.x + fA.y;
            ls1 += fB.x + fB.y;
        }
        l0 = l0 * f0 + ls0;
        l1 = l1 * f1 + ls1;
        #pragma unroll
        for (int dn = 0; dn < 16; dn++) {
            oacc[dn][0] *= f0; oacc[dn][1] *= f0;
            oacc[dn][2] *= f1; oacc[dn][3] *= f1;
        }

        // O += P V : b-frags via ldmatrix.x4.trans (covers dn, dn+1)
        #pragma unroll
        for (int kk = 0; kk < 4; kk++) {
            uint32_t a0 = p01[2 * kk], a1 = p23[2 * kk];
            uint32_t a2 = p01[2 * kk + 1], a3 = p23[2 * kk + 1];
            #pragma unroll
            for (int dn = 0; dn < 16; dn += 2) {
                uint32_t addr = vbase + (uint32_t)(kk * 16 + (lane & 15)) * KVSTR
                              + (dn + (lane >> 4)) * 16;
                uint32_t b0, b1, b2, b3;
                ldm_x4_trans(b0, b1, b2, b3, addr);
                mma_f16(oacc[dn][0], oacc[dn][1], oacc[dn][2], oacc[dn][3],
                        a0, a1, a2, a3, b0, b1);
                mma_f16(oacc[dn + 1][0], oacc[dn + 1][1], oacc[dn + 1][2], oacc[dn + 1][3],
                        a0, a1, a2, a3, b2, b3);
            }
        }
        __syncthreads();
    }

    l0 += __shfl_xor_sync(0xffffffffu, l0, 1);
    l0 += __shfl_xor_sync(0xffffffffu, l0, 2);
    l1 += __shfl_xor_sync(0xffffffffu, l1, 1);
    l1 += __shfl_xor_sync(0xffffffffu, l1, 2);
    const float inv0 = 1.f / l0, inv1 = 1.f / l1;

    __half* c0row = ctx + (size_t)(qb + g) * H_DIM + h * HD;
    __half* c8row = c0row + (size_t)8 * H_DIM;
    #pragma unroll
    for (int dn = 0; dn < 16; dn++) {
        *(__half2*)(c0row + dn * 8 + 2 * c) =
            __floats2half2_rn(oacc[dn][0] * inv0, oacc[dn][1] * inv0);
        *(__half2*)(c8row + dn * 8 + 2 * c) =
            __floats2half2_rn(oacc[dn][2] * inv1, oacc[dn][3] * inv1);
    }
}

// ============== fp16 HMMA GEMM with ldmatrix fragments: C = A*B^T ===========
#define BK 32
#define AST 80
#define A_SBYTES (128 * AST)
#define B_SBYTES (256 * AST)
#define BUF_SBYTES (A_SBYTES + B_SBYTES)
#define NBUF 3
#define GEMM_SMEM_BYTES (NBUF * BUF_SBYTES)

template <int EPI, int OUTH>
__global__ void __launch_bounds__(256, 1)
gemm_h(const __half* __restrict__ A, const __half* __restrict__ B,
       const float* __restrict__ bias, const float* __restrict__ res,
       float alpha, void* __restrict__ Cv, int M, int N, int K) {
    extern __shared__ char smem[];

    const int tid  = threadIdx.x;
    const int lane = tid & 31;
    const int wid  = tid >> 5;
    const int wm   = wid & 1;
    const int wn   = wid >> 1;
    const int g    = lane >> 2;
    const int c    = lane & 3;

    const int m0 = blockIdx.x * 128;
    const int n0 = blockIdx.y * 256;

    const uint32_t sbase = (uint32_t)__cvta_generic_to_shared(smem);
    const int row4 = tid >> 2;
    const int kc   = tid & 3;

    float acc[4][8][4];
    #pragma unroll
    for (int i = 0; i < 4; i++)
        #pragma unroll
        for (int j = 0; j < 8; j++)
            #pragma unroll
            for (int q = 0; q < 4; q++) acc[i][j][q] = 0.f;

    const int nk = K >> 5;

    auto issue = [&](int kt, int b) {
        uint32_t ab = sbase + (uint32_t)b * BUF_SBYTES;
        uint32_t bb = ab + A_SBYTES;
        const __half* ag = A + (size_t)(m0 + row4) * K + kt * BK + kc * 8;
        const __half* bg = B + (size_t)(n0 + row4) * K + kt * BK + kc * 8;
        #pragma unroll
        for (int i = 0; i < 2; i++)
            cp_async16(ab + (uint32_t)(row4 + 64 * i) * AST + kc * 16,
                       ag + (size_t)(64 * i) * K);
        #pragma unroll
        for (int i = 0; i < 4; i++)
            cp_async16(bb + (uint32_t)(row4 + 64 * i) * AST + kc * 16,
                       bg + (size_t)(64 * i) * K);
        cp_commit();
    };

    issue(0, 0);
    issue(1, 1);

    // ldmatrix address components (constant per thread)
    const int a_row = wm * 64 + (lane & 15);      // + mt*16
    const int a_cb  = (lane & 16);                // 0 | 16 bytes
    const int b_row = wn * 64 + (lane & 7) + ((lane >> 4) << 3);  // + nt*8 (pairs)
    const int b_cb  = ((lane >> 3) & 1) * 16;     // 0 | 16 bytes

    for (int kt = 0; kt < nk; kt++) {
        const int b = kt % NBUF;
        if (kt + 2 < nk) { issue(kt + 2, (kt + 2) % NBUF); cp_wait<2>(); }
        else if (kt + 1 < nk) cp_wait<1>();
        else cp_wait<0>();
        __syncthreads();

        const uint32_t As = sbase + (uint32_t)b * BUF_SBYTES;
        const uint32_t Bs = As + A_SBYTES;

        #pragma unroll
        for (int ks = 0; ks < 2; ks++) {
            const int kb = ks * 32;
            uint32_t af[4][4];
            uint32_t bf[8][2];
            #pragma unroll
            for (int mt = 0; mt < 4; mt++)
                ldm_x4(af[mt][0], af[mt][1], af[mt][2], af[mt][3],
                       As + (uint32_t)(a_row + mt * 16) * AST + kb + a_cb);
            #pragma unroll
            for (int nt = 0; nt < 8; nt += 2)
                ldm_x4(bf[nt][0], bf[nt][1], bf[nt + 1][0], bf[nt + 1][1],
                       Bs + (uint32_t)(b_row + nt * 8) * AST + kb + b_cb);
            #pragma unroll
            for (int mt = 0; mt < 4; mt++)
                #pragma unroll
                for (int nt = 0; nt < 8; nt++)
                    mma_f16(acc[mt][nt][0], acc[mt][nt][1],
                            acc[mt][nt][2], acc[mt][nt][3],
                            af[mt][0], af[mt][1], af[mt][2], af[mt][3],
                            bf[nt][0], bf[nt][1]);
        }
        __syncthreads();
    }

    #pragma unroll
    for (int mt = 0; mt < 4; mt++) {
        int r0 = m0 + wm * 64 + mt * 16 + g;
        int r1 = r0 + 8;
        #pragma unroll
        for (int nt = 0; nt < 8; nt++) {
            int col = n0 + wn * 64 + nt * 8 + 2 * c;
            float b0v = bias[col], b1v = bias[col + 1];

            float v0 = acc[mt][nt][0] + b0v;
            float v1 = acc[mt][nt][1] + b1v;
            float v2 = acc[mt][nt][2] + b0v;
            float v3 = acc[mt][nt][3] + b1v;
            if (EPI == 1) {
                v0 = gelu_tanh(v0); v1 = gelu_tanh(v1);
                v2 = gelu_tanh(v2); v3 = gelu_tanh(v3);
            }
            if (EPI == 2) {
                const float* rr0 = res + (size_t)r0 * N + col;
                const float* rr1 = res + (size_t)r1 * N + col;
                v0 += alpha * rr0[0]; v1 += alpha * rr0[1];
                v2 += alpha * rr1[0]; v3 += alpha * rr1[1];
            }
            if (OUTH) {
                __half* C = (__half*)Cv;
                *(__half2*)(C + (size_t)r0 * N + col) = __floats2half2_rn(v0, v1);
                *(__half2*)(C + (size_t)r1 * N + col) = __floats2half2_rn(v2, v3);
            } else {
                float* C = (float*)Cv;
                *(float2*)(C + (size_t)r0 * N + col) = make_float2(v0, v1);
                *(float2*)(C + (size_t)r1 * N + col) = make_float2(v2, v3);
            }
        }
    }
}

// ---------------- launch ----------------------------------------------------
extern "C" void kernel_launch(void* const* d_in, const int* in_sizes, int n_in,
                              void* d_out, int out_size) {
    const float* hidden  = (const float*)d_in[0];
    const float* cosc    = (const float*)d_in[4];
    const float* sinc    = (const float*)d_in[5];
    const float* ln1_w   = (const float*)d_in[6];
    const float* ln1_b   = (const float*)d_in[7];
    const float* qkv_w   = (const float*)d_in[8];
    const float* qkv_b   = (const float*)d_in[9];
    const float* dense_w = (const float*)d_in[10];
    const float* dense_b = (const float*)d_in[11];
    const float* ln2_w   = (const float*)d_in[12];
    const float* ln2_b   = (const float*)d_in[13];
    const float* mlp_w1  = (const float*)d_in[14];
    const float* mlp_b1  = (const float*)d_in[15];
    const float* mlp_w2  = (const float*)d_in[16];
    const float* mlp_b2  = (const float*)d_in[17];
    float* out = (float*)d_out;

    float *res1, *hid, *res2;
    __half *qkvh, *res1h, *res2h, *ctxh, *acth, *qkv_wh, *dense_wh, *w1h, *w2h;
    cudaGetSymbolAddress((void**)&res1,  g_res1);
    cudaGetSymbolAddress((void**)&hid,   g_hidden);
    cudaGetSymbolAddress((void**)&res2,  g_res2);
    cudaGetSymbolAddress((void**)&qkvh,  g_qkvh);
    cudaGetSymbolAddress((void**)&res1h, g_res1h);
    cudaGetSymbolAddress((void**)&res2h, g_res2h);
    cudaGetSymbolAddress((void**)&ctxh,  g_ctxh);
    cudaGetSymbolAddress((void**)&acth,  g_acth);
    cudaGetSymbolAddress((void**)&qkv_wh,   g_qkv_wh);
    cudaGetSymbolAddress((void**)&dense_wh, g_dense_wh);
    cudaGetSymbolAddress((void**)&w1h,      g_w1h);
    cudaGetSymbolAddress((void**)&w2h,      g_w2h);

    cudaFuncSetAttribute(gemm_h<0,1>, cudaFuncAttributeMaxDynamicSharedMemorySize, GEMM_SMEM_BYTES);
    cudaFuncSetAttribute(gemm_h<1,1>, cudaFuncAttributeMaxDynamicSharedMemorySize, GEMM_SMEM_BYTES);
    cudaFuncSetAttribute(gemm_h<2,0>, cudaFuncAttributeMaxDynamicSharedMemorySize, GEMM_SMEM_BYTES);
    cudaFuncSetAttribute(fattn_mma,   cudaFuncAttributeMaxDynamicSharedMemorySize, ATTN_SMEM);

    // --- side stream for weight conversions not needed until the dense GEMM ---
    cudaStream_t s1;
    cudaStreamCreateWithFlags(&s1, cudaStreamNonBlocking);
    cudaEvent_t eFork, eJoin;
    cudaEventCreateWithFlags(&eFork, cudaEventDisableTiming);
    cudaEventCreateWithFlags(&eJoin, cudaEventDisableTiming);

    cudaEventRecord(eFork, 0);
    cudaStreamWaitEvent(s1, eFork, 0);
    {
        int n;
        n = H_DIM * H_DIM; f2h_kernel<<<n / 1024, 256, 0, s1>>>(dense_w, dense_wh, n);
        n = INNER * H_DIM; f2h_kernel<<<n / 1024, 256, 0, s1>>>(mlp_w1,  w1h,      n);
        n = H_DIM * INNER; f2h_kernel<<<n / 1024, 256, 0, s1>>>(mlp_w2,  w2h,      n);
    }
    cudaEventRecord(eJoin, s1);

    // --- main chain ---
    // 0. qkv weight conversion (needed first)
    {
        int n = QKV3 * H_DIM;
        f2h_kernel<<<n / 1024, 256>>>(qkv_w, qkv_wh, n);
    }

    // 1. LN1
    ln_kernel<<<S_LEN, 256>>>(hidden, ln1_w, ln1_b, res1, res1h);

    // 2. QKV GEMM -> fp16 qkvh
    {
        dim3 grid(S_LEN / 128, QKV3 / 256);
        gemm_h<0,1><<<grid, 256, GEMM_SMEM_BYTES>>>(res1h, qkv_wh, qkv_b, res1, 0.f,
                                                    qkvh, S_LEN, QKV3, H_DIM);
    }

    // 3. RoPE (fp16 in-place)
    {
        dim3 grid(S_LEN, NH);
        rope_h_kernel<<<grid, 256>>>(qkvh, cosc, sinc);
    }

    // 4. HMMA flash attention (fp16 ctx out)
    {
        dim3 grid(S_LEN / 128, NH);
        fattn_mma<<<grid, 256, ATTN_SMEM>>>(qkvh, ctxh);
    }

    // join: dense/MLP weight conversions must be done from here on
    cudaStreamWaitEvent(0, eJoin, 0);

    // 5. dense GEMM + alpha*residual
    {
        dim3 grid(S_LEN / 128, H_DIM / 256);
        gemm_h<2,0><<<grid, 256, GEMM_SMEM_BYTES>>>(ctxh, dense_wh, dense_b, res1, ALPHA,
                                                    hid, S_LEN, H_DIM, H_DIM);
    }

    // 6. LN2
    ln_kernel<<<S_LEN, 256>>>(hid, ln2_w, ln2_b, res2, res2h);

    // 7. MLP up + gelu (fp16 out)
    {
        dim3 grid(S_LEN / 128, INNER / 256);
        gemm_h<1,1><<<grid, 256, GEMM_SMEM_BYTES>>>(res2h, w1h, mlp_b1, res2, 0.f,
                                                    acth, S_LEN, INNER, H_DIM);
    }

    // 8. MLP down + alpha*residual -> output
    {
        dim3 grid(S_LEN / 128, H_DIM / 256);
        gemm_h<2,0><<<grid, 256, GEMM_SMEM_BYTES>>>(acth, w2h, mlp_b2, res2, ALPHA,
                                                    out, S_LEN, H_DIM, INNER);
    }

    cudaEventDestroy(eFork);
    cudaEventDestroy(eJoin);
    cudaStreamDestroy(s1);
}